// round 10
// baseline (speedup 1.0000x reference)
#include <cuda_runtime.h>
#include <cuda_fp16.h>
#include <cstdint>

#define NPOS 16384   // 128*128 guide positions
#define LPOS 1024    // 32*32 low positions
#define DMODEL 512

// ---------------------------------------------------------------------------
// Scratch (static device globals — no allocation APIs allowed)
// ---------------------------------------------------------------------------
__device__ __half g_Af [NPOS * DMODEL];          // fp16 activations (guide, then msg)
__device__ __half g_Lf [LPOS * DMODEL];          // fp16 low activations
__device__ __half g_Whi[4 * DMODEL * DMODEL];    // weight hi (fp16)
__device__ __half g_Wlo[4 * DMODEL * DMODEL];    // weight lo (fp16 residual)
__device__ __half g_Q [NPOS * DMODEL];           // fp16 Q
__device__ __half g_K [LPOS * DMODEL];           // fp16 K
__device__ __half g_V [LPOS * DMODEL];           // fp16 V
__device__ float  g_M2[NPOS * DMODEL];

// ---------------------------------------------------------------------------
// Baseline-PTX helpers (sm_80+ features only: work on plain sm_103 target)
// ---------------------------------------------------------------------------
__device__ __forceinline__ uint32_t smem_u32(const void* p) {
    uint32_t a;
    asm("{ .reg .u64 t; cvta.to.shared.u64 t, %1; cvt.u32.u64 %0, t; }" : "=r"(a) : "l"(p));
    return a;
}

#define CP16(dst, src) \
    asm volatile("cp.async.cg.shared.global [%0], [%1], 16;" :: "r"(dst), "l"(src))
#define CP_COMMIT() asm volatile("cp.async.commit_group;" ::: "memory")
#define CP_WAIT(n)  asm volatile("cp.async.wait_group %0;" :: "n"(n) : "memory")

#define LDSM4(r0, r1, r2, r3, addr) \
    asm volatile("ldmatrix.sync.aligned.m8n8.x4.shared.b16 {%0,%1,%2,%3}, [%4];" \
        : "=r"(r0), "=r"(r1), "=r"(r2), "=r"(r3) : "r"(addr))

#define MMA16816F(d, a, b) \
    asm volatile("mma.sync.aligned.m16n8k16.row.col.f32.f16.f16.f32 " \
        "{%0,%1,%2,%3}, {%4,%5,%6,%7}, {%8,%9}, {%0,%1,%2,%3};" \
        : "+f"((d)[0]), "+f"((d)[1]), "+f"((d)[2]), "+f"((d)[3]) \
        : "r"((a)[0]), "r"((a)[1]), "r"((a)[2]), "r"((a)[3]), \
          "r"((b)[0]), "r"((b)[1]))

// ---------------------------------------------------------------------------
// mma_gemm<OutT>: C[m][n] = sum_k A[m][k]*B[n][k], K=512 fixed.
// fp32 emulation: A rounded to fp16, B = Bhi + Blo fp16 split (exact):
//   C = A*Bhi + A*Blo, fp32 accumulate. OutT = __half (QKV) or float (M2).
// CTA: 128x128 tile, 128 threads = 4 warps (2m x 2n), warp tile 64x64.
// K chunks of 32, 3 smem buffers, single barrier per chunk, 2 CTAs/SM.
// Three independent GEMMs selected by blockIdx.z; CTAs with
// blockIdx.y >= mtiles exit immediately (QKV share one launch).
// ---------------------------------------------------------------------------
#define PITCH 80
#define TILE_B (128 * PITCH)            // 10240 B per operand tile
#define STAGE_B (3 * TILE_B)            // A, Bhi, Blo = 30720 B per stage
#define NSTAGE 3

struct GemmArgs {
    const __half* A;
    const __half* Bhi;
    const __half* Blo;
    void* C;
    int mtiles;
};

template<typename OutT>
__global__ __launch_bounds__(128, 2)
void mma_gemm(GemmArgs g0, GemmArgs g1, GemmArgs g2)
{
    const GemmArgs& ga_ = (blockIdx.z == 0) ? g0 : (blockIdx.z == 1) ? g1 : g2;
    if ((int)blockIdx.y >= ga_.mtiles) return;

    const __half* __restrict__ A   = ga_.A;
    const __half* __restrict__ Bhi = ga_.Bhi;
    const __half* __restrict__ Blo = ga_.Blo;
    OutT* __restrict__ C = (OutT*)ga_.C;

    extern __shared__ char smem[];
    const uint32_t sb = smem_u32(smem);

    const int tid  = threadIdx.x;
    const int wid  = tid >> 5;
    const int lane = tid & 31;
    const int bm0  = blockIdx.y * 128;
    const int bn0  = blockIdx.x * 128;
    const int wm   = (wid >> 1) * 64;    // warp m offset in tile
    const int wn   = (wid & 1) * 64;     // warp n offset in tile

    float acc[4][8][4];
#pragma unroll
    for (int i = 0; i < 4; i++)
#pragma unroll
        for (int j = 0; j < 8; j++)
#pragma unroll
            for (int r = 0; r < 4; r++) acc[i][j][r] = 0.f;

    // ---- async stage loader: 12 x 16B per thread per stage
    auto load_stage = [&](int s, int k0) {
        const uint32_t base = sb + s * STAGE_B;
#pragma unroll
        for (int i = 0; i < 4; i++) {
            const int idx = tid + 128 * i;        // 0..511
            const int row = idx >> 2;             // 0..127
            const int c   = idx & 3;              // 16B chunk in 64B row
            const uint32_t off = row * PITCH + c * 16;
            const size_t ga = ((size_t)(bm0 + row) * 512 + k0) * 2 + c * 16;
            const size_t gb = ((size_t)(bn0 + row) * 512 + k0) * 2 + c * 16;
            CP16(base + off,              (const char*)A   + ga);
            CP16(base + TILE_B + off,     (const char*)Bhi + gb);
            CP16(base + 2 * TILE_B + off, (const char*)Blo + gb);
        }
        CP_COMMIT();
    };

    // ---- compute one k32 chunk from stage s
    auto compute_stage = [&](int s) {
        const uint32_t base = sb + s * STAGE_B;
#pragma unroll
        for (int kk = 0; kk < 2; kk++) {          // two k16 halves
            const uint32_t koff = kk * 32;        // byte offset of k16 half

            uint32_t a[4][4];
#pragma unroll
            for (int f = 0; f < 4; f++) {
                const uint32_t ra = base +
                    (uint32_t)(wm + f * 16 + (lane & 15)) * PITCH +
                    koff + ((lane >> 4) << 4);
                LDSM4(a[f][0], a[f][1], a[f][2], a[f][3], ra);
            }

            uint32_t bh[8][2], bl[8][2];
#pragma unroll
            for (int g = 0; g < 4; g++) {
                const uint32_t rb = base + TILE_B +
                    (uint32_t)(wn + g * 16 + (lane & 7) + ((lane >> 4) << 3)) * PITCH +
                    koff + (((lane >> 3) & 1) << 4);
                LDSM4(bh[2*g][0], bh[2*g][1], bh[2*g+1][0], bh[2*g+1][1], rb);
                LDSM4(bl[2*g][0], bl[2*g][1], bl[2*g+1][0], bl[2*g+1][1], rb + TILE_B);
            }

#pragma unroll
            for (int f = 0; f < 4; f++)
#pragma unroll
                for (int g = 0; g < 8; g++) {
                    MMA16816F(acc[f][g], a[f], bh[g]);
                    MMA16816F(acc[f][g], a[f], bl[g]);
                }
        }
    };

    // ---- prologue: 2 chunks in flight
    load_stage(0, 0);
    load_stage(1, 32);

#pragma unroll
    for (int c = 0; c < 16; c++) {
        if (c < 15) { CP_WAIT(1); } else { CP_WAIT(0); }
        __syncthreads();
        if (c + 2 < 16) load_stage((c + 2) % NSTAGE, (c + 2) * 32);
        compute_stage(c % NSTAGE);
    }

    // ---- epilogue: acc -> C (row stride 512), fp32 or fp16 per OutT
    const int qrow = lane >> 2;          // 0..7
    const int qcol = (lane & 3) * 2;     // 0,2,4,6
#pragma unroll
    for (int f = 0; f < 4; f++)
#pragma unroll
        for (int g = 0; g < 8; g++) {
            const int row = bm0 + wm + f * 16 + qrow;
            const int col = bn0 + wn + g * 8 + qcol;
            if (sizeof(OutT) == 4) {
                *(float2*)((float*)C + (size_t)row * 512 + col) =
                    make_float2(acc[f][g][0], acc[f][g][1]);
                *(float2*)((float*)C + (size_t)(row + 8) * 512 + col) =
                    make_float2(acc[f][g][2], acc[f][g][3]);
            } else {
                *(__half2*)((__half*)C + (size_t)row * 512 + col) =
                    __floats2half2_rn(acc[f][g][0], acc[f][g][1]);
                *(__half2*)((__half*)C + (size_t)(row + 8) * 512 + col) =
                    __floats2half2_rn(acc[f][g][2], acc[f][g][3]);
            }
        }
}

// ---------------------------------------------------------------------------
// convT: in fp32 [512][M] (channel-major) -> fp16 [M][512] (transpose+round).
// ---------------------------------------------------------------------------
__global__ __launch_bounds__(256)
void convT_kernel(const float* __restrict__ in, __half* __restrict__ outp, int M)
{
    __shared__ float t[32][33];
    const int tx = threadIdx.x, ty = threadIdx.y;
    const int mb = blockIdx.x * 32, kb = blockIdx.y * 32;
#pragma unroll
    for (int j = 0; j < 4; j++)
        t[ty + 8 * j][tx] = in[(size_t)(kb + ty + 8 * j) * M + mb + tx];
    __syncthreads();
#pragma unroll
    for (int j = 0; j < 4; j++) {
        const float v = t[tx][ty + 8 * j];
        outp[(size_t)(mb + ty + 8 * j) * 512 + kb + tx] = __float2half(v);
    }
}

// ---------------------------------------------------------------------------
// conv_w: all 4 weights in one launch (blockIdx.z selects). fp32 -> hi/lo fp16.
// ---------------------------------------------------------------------------
__global__ __launch_bounds__(256)
void conv_w_kernel(const float4* __restrict__ w0, const float4* __restrict__ w1,
                   const float4* __restrict__ w2, const float4* __restrict__ w3,
                   __half* __restrict__ whi, __half* __restrict__ wlo)
{
    const int z = blockIdx.z;
    const float4* src = (z == 0) ? w0 : (z == 1) ? w1 : (z == 2) ? w2 : w3;
    const int i = blockIdx.x * 256 + threadIdx.x;        // 0..65535
    const float4 v = src[i];

    const __half hx = __float2half(v.x), hy = __float2half(v.y);
    const __half hz = __float2half(v.z), hw = __float2half(v.w);
    const __half lx = __float2half(v.x - __half2float(hx));
    const __half ly = __float2half(v.y - __half2float(hy));
    const __half lz = __float2half(v.z - __half2float(hz));
    const __half lw = __float2half(v.w - __half2float(hw));

    const size_t o = (size_t)z * (DMODEL * DMODEL / 4) + i;
    ((ushort4*)whi)[o] = make_ushort4(__half_as_ushort(hx), __half_as_ushort(hy),
                                      __half_as_ushort(hz), __half_as_ushort(hw));
    ((ushort4*)wlo)[o] = make_ushort4(__half_as_ushort(lx), __half_as_ushort(ly),
                                      __half_as_ushort(lz), __half_as_ushort(lw));
}

// ---------------------------------------------------------------------------
// Windowed attention, 256 threads: tid = head*32 + half*16 + pos.
// Q/K/V are fp16; K/V converted to fp32 in smem at staging, Q via half2
// loads. All arithmetic fp32 (unchanged). Writes fp16 msg.
// ---------------------------------------------------------------------------
__global__ __launch_bounds__(256)
void attn_kernel(const __half* __restrict__ Q, const __half* __restrict__ Km,
                 const __half* __restrict__ Vm, __half* __restrict__ msg)
{
    __shared__ float Ks[9][512];
    __shared__ float Vs[9][512];

    const int tx = blockIdx.x;
    const int ty = blockIdx.y;
    const int tid = threadIdx.x;

    for (int idx = tid; idx < 9 * 128; idx += 256) {
        const int k  = idx >> 7;
        const int c4 = idx & 127;          // float4 slot (4 elems)
        const int yy = min(max(ty - 1 + k / 3, 0), 31);
        const int xx = min(max(tx - 1 + k % 3, 0), 31);
        const int p  = yy * 32 + xx;
        const __half2* ks = (const __half2*)(Km + (size_t)p * 512) + c4 * 2;
        const __half2* vs = (const __half2*)(Vm + (size_t)p * 512) + c4 * 2;
        const float2 k0 = __half22float2(ks[0]);
        const float2 k1 = __half22float2(ks[1]);
        const float2 v0 = __half22float2(vs[0]);
        const float2 v1 = __half22float2(vs[1]);
        ((float4*)&Ks[k][0])[c4] = make_float4(k0.x, k0.y, k1.x, k1.y);
        ((float4*)&Vs[k][0])[c4] = make_float4(v0.x, v0.y, v1.x, v1.y);
    }
    __syncthreads();

    const int pos  = tid & 15;           // 0..15
    const int half = (tid >> 4) & 1;     // 0..1
    const int head = tid >> 5;           // 0..7
    const int n = (ty * 4 + (pos >> 2)) * 128 + tx * 4 + (pos & 3);
    const int coff = head * 64 + half * 32;   // this thread's 32 channels

    const __half2* q2 = (const __half2*)(Q + (size_t)n * 512 + coff);

    float acc[9];
#pragma unroll
    for (int k = 0; k < 9; k++) acc[k] = 0.f;

#pragma unroll
    for (int e = 0; e < 8; e++) {
        const float2 qa = __half22float2(q2[2 * e]);
        const float2 qb = __half22float2(q2[2 * e + 1]);
#pragma unroll
        for (int k = 0; k < 9; k++) {
            float4 kv = ((const float4*)&Ks[k][coff])[e];
            acc[k] += qa.x * kv.x + qa.y * kv.y + qb.x * kv.z + qb.y * kv.w;
        }
    }
    // combine the two halves (threads tid and tid^16 share a warp)
#pragma unroll
    for (int k = 0; k < 9; k++)
        acc[k] += __shfl_xor_sync(0xffffffffu, acc[k], 16);

    float mx = acc[0];
#pragma unroll
    for (int k = 1; k < 9; k++) mx = fmaxf(mx, acc[k]);
    float s = 0.f;
#pragma unroll
    for (int k = 0; k < 9; k++) { acc[k] = __expf(0.125f * (acc[k] - mx)); s += acc[k]; }
    const float inv = 1.f / s;
#pragma unroll
    for (int k = 0; k < 9; k++) acc[k] *= inv;

    __half* outp = msg + (size_t)n * 512 + coff;
#pragma unroll
    for (int e = 0; e < 8; e++) {
        float4 o = make_float4(0.f, 0.f, 0.f, 0.f);
#pragma unroll
        for (int k = 0; k < 9; k++) {
            float4 vv = ((const float4*)&Vs[k][coff])[e];
            o.x += acc[k] * vv.x;
            o.y += acc[k] * vv.y;
            o.z += acc[k] * vv.z;
            o.w += acc[k] * vv.w;
        }
        const __half2 h0 = __floats2half2_rn(o.x, o.y);
        const __half2 h1 = __floats2half2_rn(o.z, o.w);
        uint2 pk;
        pk.x = *(const uint32_t*)&h0;
        pk.y = *(const uint32_t*)&h1;
        *(uint2*)(outp + e * 4) = pk;
    }
}

// ---------------------------------------------------------------------------
// LayerNorm over d=512 per position + transpose to channel-major output.
// ---------------------------------------------------------------------------
__global__ __launch_bounds__(256)
void ln_kernel(const float* __restrict__ X, const float* __restrict__ gamma,
               const float* __restrict__ beta, float* __restrict__ out)
{
    __shared__ float sm[16 * 513];

    const int nb   = blockIdx.x * 16;
    const int warp = threadIdx.x >> 5;
    const int lane = threadIdx.x & 31;

    for (int r = warp; r < 16; r += 8) {
        const int n = nb + r;
        const float* row = X + (size_t)n * 512;
        float v[16];
        float s = 0.f;
#pragma unroll
        for (int j = 0; j < 16; j++) { v[j] = row[lane + 32 * j]; s += v[j]; }
#pragma unroll
        for (int o = 16; o > 0; o >>= 1) s += __shfl_xor_sync(0xffffffffu, s, o);
        const float mu = s * (1.f / 512.f);
        float q = 0.f;
#pragma unroll
        for (int j = 0; j < 16; j++) { float d = v[j] - mu; q += d * d; }
#pragma unroll
        for (int o = 16; o > 0; o >>= 1) q += __shfl_xor_sync(0xffffffffu, q, o);
        const float rstd = rsqrtf(q * (1.f / 512.f) + 1e-5f);
#pragma unroll
        for (int j = 0; j < 16; j++) {
            const int o = lane + 32 * j;
            sm[r * 513 + o] = (v[j] - mu) * rstd * gamma[o] + beta[o];
        }
    }
    __syncthreads();

    const int i  = threadIdx.x & 15;
    const int ob = threadIdx.x >> 4;
    for (int o = ob; o < 512; o += 16)
        out[(size_t)o * 16384 + nb + i] = sm[i * 513 + o];
}

// ---------------------------------------------------------------------------
extern "C" void kernel_launch(void* const* d_in, const int* in_sizes, int n_in,
                              void* d_out, int out_size)
{
    const float* low   = (const float*)d_in[0];
    const float* guide = (const float*)d_in[1];
    const float* Wq    = (const float*)d_in[2];
    const float* Wk    = (const float*)d_in[3];
    const float* Wv    = (const float*)d_in[4];
    const float* Wm    = (const float*)d_in[5];
    const float* gamma = (const float*)d_in[6];
    const float* beta  = (const float*)d_in[7];
    float* out = (float*)d_out;

    __half *Af, *Lf, *Whi, *Wlo, *Q, *K, *V;
    float *M2;
    cudaGetSymbolAddress((void**)&Af,  g_Af);
    cudaGetSymbolAddress((void**)&Lf,  g_Lf);
    cudaGetSymbolAddress((void**)&Whi, g_Whi);
    cudaGetSymbolAddress((void**)&Wlo, g_Wlo);
    cudaGetSymbolAddress((void**)&Q,   g_Q);
    cudaGetSymbolAddress((void**)&K,   g_K);
    cudaGetSymbolAddress((void**)&V,   g_V);
    cudaGetSymbolAddress((void**)&M2,  g_M2);

    const int W_ELEMS = DMODEL * DMODEL;       // 262144
    const int GEMM_SMEM = NSTAGE * STAGE_B;    // 92160 B

    cudaFuncSetAttribute(mma_gemm<__half>, cudaFuncAttributeMaxDynamicSharedMemorySize,
                         GEMM_SMEM);
    cudaFuncSetAttribute(mma_gemm<float>, cudaFuncAttributeMaxDynamicSharedMemorySize,
                         GEMM_SMEM);

    // Convert + transpose activations (channel-major fp32 -> row-major fp16)
    convT_kernel<<<dim3(NPOS / 32, 16), dim3(32, 8)>>>(guide, Af, NPOS);
    convT_kernel<<<dim3(LPOS / 32, 16), dim3(32, 8)>>>(low, Lf, LPOS);

    // Convert all 4 weights in one launch: slots 0=Wq, 1=Wk, 2=Wv, 3=Wm
    conv_w_kernel<<<dim3(W_ELEMS / 4 / 256, 1, 4), 256>>>(
        (const float4*)Wq, (const float4*)Wk, (const float4*)Wv, (const float4*)Wm,
        Whi, Wlo);

    // Q, K, V projections in ONE launch (z selects; y-overrun CTAs exit), fp16 out
    {
        GemmArgs gq = { Af, Whi,               Wlo,               Q, 128 };
        GemmArgs gk = { Lf, Whi + 1 * W_ELEMS, Wlo + 1 * W_ELEMS, K, 8 };
        GemmArgs gv = { Lf, Whi + 2 * W_ELEMS, Wlo + 2 * W_ELEMS, V, 8 };
        mma_gemm<__half><<<dim3(4, 128, 3), 128, GEMM_SMEM>>>(gq, gk, gv);
    }

    // Windowed attention -> fp16 msg directly into Af (guide no longer needed)
    attn_kernel<<<dim3(32, 32), 256>>>(Q, K, V, Af);

    // M2 = msg @ Wm^T (fp32 out for LayerNorm)
    {
        GemmArgs gm = { Af, Whi + 3 * W_ELEMS, Wlo + 3 * W_ELEMS, M2, 128 };
        mma_gemm<float><<<dim3(4, 128, 1), 128, GEMM_SMEM>>>(gm, gm, gm);
    }

    // LayerNorm + transpose to channel-major output
    ln_kernel<<<1024, 256>>>(M2, gamma, beta, out);
}

// round 11
// speedup vs baseline: 1.7630x; 1.7630x over previous
#include <cuda_runtime.h>
#include <cuda_fp16.h>
#include <cstdint>

#define NPOS 16384   // 128*128 guide positions
#define LPOS 1024    // 32*32 low positions
#define DMODEL 512

// ---------------------------------------------------------------------------
// Scratch (static device globals — no allocation APIs allowed)
// ---------------------------------------------------------------------------
__device__ __half g_Af [NPOS * DMODEL];          // fp16 activations (guide, then msg)
__device__ __half g_Lf [LPOS * DMODEL];          // fp16 low activations
__device__ __half g_Whi[4 * DMODEL * DMODEL];    // weight hi (fp16)
__device__ __half g_Wlo[4 * DMODEL * DMODEL];    // weight lo (fp16 residual)
__device__ float g_Q [NPOS * DMODEL];
__device__ float g_K [LPOS * DMODEL];
__device__ float g_V [LPOS * DMODEL];
__device__ float g_M2[NPOS * DMODEL];

// ---------------------------------------------------------------------------
// Baseline-PTX helpers (sm_80+ features only: work on plain sm_103 target)
// ---------------------------------------------------------------------------
__device__ __forceinline__ uint32_t smem_u32(const void* p) {
    uint32_t a;
    asm("{ .reg .u64 t; cvta.to.shared.u64 t, %1; cvt.u32.u64 %0, t; }" : "=r"(a) : "l"(p));
    return a;
}

#define CP16(dst, src) \
    asm volatile("cp.async.cg.shared.global [%0], [%1], 16;" :: "r"(dst), "l"(src))
#define CP_COMMIT() asm volatile("cp.async.commit_group;" ::: "memory")
#define CP_WAIT(n)  asm volatile("cp.async.wait_group %0;" :: "n"(n) : "memory")

#define LDSM4(r0, r1, r2, r3, addr) \
    asm volatile("ldmatrix.sync.aligned.m8n8.x4.shared.b16 {%0,%1,%2,%3}, [%4];" \
        : "=r"(r0), "=r"(r1), "=r"(r2), "=r"(r3) : "r"(addr))

#define MMA16816F(d, a, b) \
    asm volatile("mma.sync.aligned.m16n8k16.row.col.f32.f16.f16.f32 " \
        "{%0,%1,%2,%3}, {%4,%5,%6,%7}, {%8,%9}, {%0,%1,%2,%3};" \
        : "+f"((d)[0]), "+f"((d)[1]), "+f"((d)[2]), "+f"((d)[3]) \
        : "r"((a)[0]), "r"((a)[1]), "r"((a)[2]), "r"((a)[3]), \
          "r"((b)[0]), "r"((b)[1]))

// ---------------------------------------------------------------------------
// mma_gemm<USE_LO>: C[m][n] = sum_k A[m][k]*B[n][k], K=512, fp32 out.
// USE_LO=1: B = Bhi + Blo fp16 split (exact weights)  -> 2 MMAs per k16.
// USE_LO=0: B = Bhi only (weights rounded to fp16)    -> 1 MMA per k16.
// CTA: 128x128 tile, 128 threads = 4 warps (2m x 2n), warp tile 64x64.
// K chunks of 32, 3 smem buffers, single barrier per chunk, 2 CTAs/SM.
// Three independent GEMMs selected by blockIdx.z; CTAs with
// blockIdx.y >= mtiles exit immediately (QKV share one launch).
// ---------------------------------------------------------------------------
#define PITCH 80
#define TILE_B (128 * PITCH)            // 10240 B per operand tile
#define NSTAGE 3

struct GemmArgs {
    const __half* A;
    const __half* Bhi;
    const __half* Blo;
    float* C;
    int mtiles;
};

template<int USE_LO>
__global__ __launch_bounds__(128, 2)
void mma_gemm(GemmArgs g0, GemmArgs g1, GemmArgs g2)
{
    constexpr int NT = USE_LO ? 3 : 2;            // tiles per stage
    constexpr int STAGE_B = NT * TILE_B;

    const GemmArgs& ga_ = (blockIdx.z == 0) ? g0 : (blockIdx.z == 1) ? g1 : g2;
    if ((int)blockIdx.y >= ga_.mtiles) return;

    const __half* __restrict__ A   = ga_.A;
    const __half* __restrict__ Bhi = ga_.Bhi;
    const __half* __restrict__ Blo = ga_.Blo;
    float* __restrict__ C = ga_.C;

    extern __shared__ char smem[];
    const uint32_t sb = smem_u32(smem);

    const int tid  = threadIdx.x;
    const int wid  = tid >> 5;
    const int lane = tid & 31;
    const int bm0  = blockIdx.y * 128;
    const int bn0  = blockIdx.x * 128;
    const int wm   = (wid >> 1) * 64;    // warp m offset in tile
    const int wn   = (wid & 1) * 64;     // warp n offset in tile

    float acc[4][8][4];
#pragma unroll
    for (int i = 0; i < 4; i++)
#pragma unroll
        for (int j = 0; j < 8; j++)
#pragma unroll
            for (int r = 0; r < 4; r++) acc[i][j][r] = 0.f;

    // ---- async stage loader: NT x 4 x 16B per thread per stage
    auto load_stage = [&](int s, int k0) {
        const uint32_t base = sb + s * STAGE_B;
#pragma unroll
        for (int i = 0; i < 4; i++) {
            const int idx = tid + 128 * i;        // 0..511
            const int row = idx >> 2;             // 0..127
            const int c   = idx & 3;              // 16B chunk in 64B row
            const uint32_t off = row * PITCH + c * 16;
            const size_t ga = ((size_t)(bm0 + row) * 512 + k0) * 2 + c * 16;
            const size_t gb = ((size_t)(bn0 + row) * 512 + k0) * 2 + c * 16;
            CP16(base + off,          (const char*)A   + ga);
            CP16(base + TILE_B + off, (const char*)Bhi + gb);
            if (USE_LO)
                CP16(base + 2 * TILE_B + off, (const char*)Blo + gb);
        }
        CP_COMMIT();
    };

    // ---- compute one k32 chunk from stage s
    auto compute_stage = [&](int s) {
        const uint32_t base = sb + s * STAGE_B;
#pragma unroll
        for (int kk = 0; kk < 2; kk++) {          // two k16 halves
            const uint32_t koff = kk * 32;        // byte offset of k16 half

            uint32_t a[4][4];
#pragma unroll
            for (int f = 0; f < 4; f++) {
                const uint32_t ra = base +
                    (uint32_t)(wm + f * 16 + (lane & 15)) * PITCH +
                    koff + ((lane >> 4) << 4);
                LDSM4(a[f][0], a[f][1], a[f][2], a[f][3], ra);
            }

            uint32_t bh[8][2], bl[8][2];
#pragma unroll
            for (int g = 0; g < 4; g++) {
                const uint32_t rb = base + TILE_B +
                    (uint32_t)(wn + g * 16 + (lane & 7) + ((lane >> 4) << 3)) * PITCH +
                    koff + (((lane >> 3) & 1) << 4);
                LDSM4(bh[2*g][0], bh[2*g][1], bh[2*g+1][0], bh[2*g+1][1], rb);
                if (USE_LO)
                    LDSM4(bl[2*g][0], bl[2*g][1], bl[2*g+1][0], bl[2*g+1][1], rb + TILE_B);
            }

#pragma unroll
            for (int f = 0; f < 4; f++)
#pragma unroll
                for (int g = 0; g < 8; g++) {
                    MMA16816F(acc[f][g], a[f], bh[g]);
                    if (USE_LO)
                        MMA16816F(acc[f][g], a[f], bl[g]);
                }
        }
    };

    // ---- prologue: 2 chunks in flight
    load_stage(0, 0);
    load_stage(1, 32);

#pragma unroll
    for (int c = 0; c < 16; c++) {
        if (c < 15) { CP_WAIT(1); } else { CP_WAIT(0); }
        __syncthreads();
        if (c + 2 < 16) load_stage((c + 2) % NSTAGE, (c + 2) * 32);
        compute_stage(c % NSTAGE);
    }

    // ---- epilogue: acc -> C (fp32, row stride 512)
    const int qrow = lane >> 2;          // 0..7
    const int qcol = (lane & 3) * 2;     // 0,2,4,6
#pragma unroll
    for (int f = 0; f < 4; f++)
#pragma unroll
        for (int g = 0; g < 8; g++) {
            const int row = bm0 + wm + f * 16 + qrow;
            const int col = bn0 + wn + g * 8 + qcol;
            *(float2*)(C + (size_t)row * 512 + col) =
                make_float2(acc[f][g][0], acc[f][g][1]);
            *(float2*)(C + (size_t)(row + 8) * 512 + col) =
                make_float2(acc[f][g][2], acc[f][g][3]);
        }
}

// ---------------------------------------------------------------------------
// conv_all: ALL input conversion in one launch. 1-D grid, 256 threads.
//   blocks [0, 8192)     : guide transpose tiles (512 x 16)   fp32->fp16
//   blocks [8192, 8704)  : low transpose tiles   (32 x 16)
//   blocks [8704, 9728)  : weight hi/lo split    (4 x 256)
// ---------------------------------------------------------------------------
__global__ __launch_bounds__(256)
void conv_all(const float* __restrict__ guide, const float* __restrict__ low,
              const float4* __restrict__ w0, const float4* __restrict__ w1,
              const float4* __restrict__ w2, const float4* __restrict__ w3,
              __half* __restrict__ Af, __half* __restrict__ Lf,
              __half* __restrict__ whi, __half* __restrict__ wlo)
{
    const int b = blockIdx.x;
    const int tid = threadIdx.x;

    if (b < 8704) {
        // ---- transpose+convert: channel-major fp32 -> row-major fp16
        const float* in;
        __half* outp;
        int M, mtile, ktile;
        if (b < 8192) { in = guide; outp = Af; M = NPOS; mtile = b & 511; ktile = b >> 9; }
        else { const int id = b - 8192; in = low; outp = Lf; M = LPOS; mtile = id & 31; ktile = id >> 5; }

        __shared__ float t[32][33];
        const int tx = tid & 31, ty = tid >> 5;      // 32 x 8
        const int mb = mtile * 32, kb = ktile * 32;
#pragma unroll
        for (int j = 0; j < 4; j++)
            t[ty + 8 * j][tx] = in[(size_t)(kb + ty + 8 * j) * M + mb + tx];
        __syncthreads();
#pragma unroll
        for (int j = 0; j < 4; j++) {
            const float v = t[tx][ty + 8 * j];
            outp[(size_t)(mb + ty + 8 * j) * 512 + kb + tx] = __float2half(v);
        }
    } else {
        // ---- weights: fp32 -> hi/lo fp16
        const int id = b - 8704;                 // 0..1023
        const int z = id >> 8;
        const float4* src = (z == 0) ? w0 : (z == 1) ? w1 : (z == 2) ? w2 : w3;
        const int i = (id & 255) * 256 + tid;    // 0..65535
        const float4 v = src[i];

        const __half hx = __float2half(v.x), hy = __float2half(v.y);
        const __half hz = __float2half(v.z), hw = __float2half(v.w);
        const __half lx = __float2half(v.x - __half2float(hx));
        const __half ly = __float2half(v.y - __half2float(hy));
        const __half lz = __float2half(v.z - __half2float(hz));
        const __half lw = __float2half(v.w - __half2float(hw));

        const size_t o = (size_t)z * (DMODEL * DMODEL / 4) + i;
        ((ushort4*)whi)[o] = make_ushort4(__half_as_ushort(hx), __half_as_ushort(hy),
                                          __half_as_ushort(hz), __half_as_ushort(hw));
        ((ushort4*)wlo)[o] = make_ushort4(__half_as_ushort(lx), __half_as_ushort(ly),
                                          __half_as_ushort(lz), __half_as_ushort(lw));
    }
}

// ---------------------------------------------------------------------------
// Windowed attention, 256 threads: tid = head*32 + half*16 + pos.
// (pos,head) pair splits the 64-elem head dim across two same-warp threads
// (shfl_xor 16 combines score partials); each thread emits 32 out channels.
// One block per 4x4 guide tile (shared 3x3 window). Writes fp16.
// ---------------------------------------------------------------------------
__global__ __launch_bounds__(256)
void attn_kernel(const float* __restrict__ Q, const float* __restrict__ Km,
                 const float* __restrict__ Vm, __half* __restrict__ msg)
{
    __shared__ float Ks[9][512];
    __shared__ float Vs[9][512];

    const int tx = blockIdx.x;
    const int ty = blockIdx.y;
    const int tid = threadIdx.x;

    for (int idx = tid; idx < 9 * 128; idx += 256) {
        const int k  = idx >> 7;
        const int c4 = idx & 127;
        const int yy = min(max(ty - 1 + k / 3, 0), 31);
        const int xx = min(max(tx - 1 + k % 3, 0), 31);
        const int p  = yy * 32 + xx;
        ((float4*)&Ks[k][0])[c4] = ((const float4*)(Km + (size_t)p * 512))[c4];
        ((float4*)&Vs[k][0])[c4] = ((const float4*)(Vm + (size_t)p * 512))[c4];
    }
    __syncthreads();

    const int pos  = tid & 15;           // 0..15
    const int half = (tid >> 4) & 1;     // 0..1
    const int head = tid >> 5;           // 0..7
    const int n = (ty * 4 + (pos >> 2)) * 128 + tx * 4 + (pos & 3);
    const int coff = head * 64 + half * 32;   // this thread's 32 channels

    const float4* q4 = (const float4*)(Q + (size_t)n * 512 + coff);

    float acc[9];
#pragma unroll
    for (int k = 0; k < 9; k++) acc[k] = 0.f;

#pragma unroll
    for (int e = 0; e < 8; e++) {
        float4 qv = q4[e];
#pragma unroll
        for (int k = 0; k < 9; k++) {
            float4 kv = ((const float4*)&Ks[k][coff])[e];
            acc[k] += qv.x * kv.x + qv.y * kv.y + qv.z * kv.z + qv.w * kv.w;
        }
    }
    // combine the two halves (threads tid and tid^16 share a warp)
#pragma unroll
    for (int k = 0; k < 9; k++)
        acc[k] += __shfl_xor_sync(0xffffffffu, acc[k], 16);

    float mx = acc[0];
#pragma unroll
    for (int k = 1; k < 9; k++) mx = fmaxf(mx, acc[k]);
    float s = 0.f;
#pragma unroll
    for (int k = 0; k < 9; k++) { acc[k] = __expf(0.125f * (acc[k] - mx)); s += acc[k]; }
    const float inv = 1.f / s;
#pragma unroll
    for (int k = 0; k < 9; k++) acc[k] *= inv;

    __half* outp = msg + (size_t)n * 512 + coff;
#pragma unroll
    for (int e = 0; e < 8; e++) {
        float4 o = make_float4(0.f, 0.f, 0.f, 0.f);
#pragma unroll
        for (int k = 0; k < 9; k++) {
            float4 vv = ((const float4*)&Vs[k][coff])[e];
            o.x += acc[k] * vv.x;
            o.y += acc[k] * vv.y;
            o.z += acc[k] * vv.z;
            o.w += acc[k] * vv.w;
        }
        const __half2 h0 = __floats2half2_rn(o.x, o.y);
        const __half2 h1 = __floats2half2_rn(o.z, o.w);
        uint2 pk;
        pk.x = *(const uint32_t*)&h0;
        pk.y = *(const uint32_t*)&h1;
        *(uint2*)(outp + e * 4) = pk;
    }
}

// ---------------------------------------------------------------------------
// LayerNorm over d=512 per position + transpose to channel-major output.
// ---------------------------------------------------------------------------
__global__ __launch_bounds__(256)
void ln_kernel(const float* __restrict__ X, const float* __restrict__ gamma,
               const float* __restrict__ beta, float* __restrict__ out)
{
    __shared__ float sm[16 * 513];

    const int nb   = blockIdx.x * 16;
    const int warp = threadIdx.x >> 5;
    const int lane = threadIdx.x & 31;

    for (int r = warp; r < 16; r += 8) {
        const int n = nb + r;
        const float* row = X + (size_t)n * 512;
        float v[16];
        float s = 0.f;
#pragma unroll
        for (int j = 0; j < 16; j++) { v[j] = row[lane + 32 * j]; s += v[j]; }
#pragma unroll
        for (int o = 16; o > 0; o >>= 1) s += __shfl_xor_sync(0xffffffffu, s, o);
        const float mu = s * (1.f / 512.f);
        float q = 0.f;
#pragma unroll
        for (int j = 0; j < 16; j++) { float d = v[j] - mu; q += d * d; }
#pragma unroll
        for (int o = 16; o > 0; o >>= 1) q += __shfl_xor_sync(0xffffffffu, q, o);
        const float rstd = rsqrtf(q * (1.f / 512.f) + 1e-5f);
#pragma unroll
        for (int j = 0; j < 16; j++) {
            const int o = lane + 32 * j;
            sm[r * 513 + o] = (v[j] - mu) * rstd * gamma[o] + beta[o];
        }
    }
    __syncthreads();

    const int i  = threadIdx.x & 15;
    const int ob = threadIdx.x >> 4;
    for (int o = ob; o < 512; o += 16)
        out[(size_t)o * 16384 + nb + i] = sm[i * 513 + o];
}

// ---------------------------------------------------------------------------
extern "C" void kernel_launch(void* const* d_in, const int* in_sizes, int n_in,
                              void* d_out, int out_size)
{
    const float* low   = (const float*)d_in[0];
    const float* guide = (const float*)d_in[1];
    const float* Wq    = (const float*)d_in[2];
    const float* Wk    = (const float*)d_in[3];
    const float* Wv    = (const float*)d_in[4];
    const float* Wm    = (const float*)d_in[5];
    const float* gamma = (const float*)d_in[6];
    const float* beta  = (const float*)d_in[7];
    float* out = (float*)d_out;

    __half *Af, *Lf, *Whi, *Wlo;
    float *Q, *K, *V, *M2;
    cudaGetSymbolAddress((void**)&Af,  g_Af);
    cudaGetSymbolAddress((void**)&Lf,  g_Lf);
    cudaGetSymbolAddress((void**)&Whi, g_Whi);
    cudaGetSymbolAddress((void**)&Wlo, g_Wlo);
    cudaGetSymbolAddress((void**)&Q,   g_Q);
    cudaGetSymbolAddress((void**)&K,   g_K);
    cudaGetSymbolAddress((void**)&V,   g_V);
    cudaGetSymbolAddress((void**)&M2,  g_M2);

    const int W_ELEMS = DMODEL * DMODEL;              // 262144
    const int SMEM_HI = NSTAGE * 2 * TILE_B;          // 61440 (USE_LO=0)
    const int SMEM_LO = NSTAGE * 3 * TILE_B;          // 92160 (USE_LO=1)

    cudaFuncSetAttribute(mma_gemm<0>, cudaFuncAttributeMaxDynamicSharedMemorySize,
                         SMEM_HI);
    cudaFuncSetAttribute(mma_gemm<1>, cudaFuncAttributeMaxDynamicSharedMemorySize,
                         SMEM_LO);

    // ALL conversions in one launch
    conv_all<<<9728, 256>>>(guide, low,
                            (const float4*)Wq, (const float4*)Wk,
                            (const float4*)Wv, (const float4*)Wm,
                            Af, Lf, Whi, Wlo);

    // Q, K, V projections in ONE launch, hi-only weights (1 MMA per k16)
    {
        GemmArgs gq = { Af, Whi,               Wlo,               Q, 128 };
        GemmArgs gk = { Lf, Whi + 1 * W_ELEMS, Wlo + 1 * W_ELEMS, K, 8 };
        GemmArgs gv = { Lf, Whi + 2 * W_ELEMS, Wlo + 2 * W_ELEMS, V, 8 };
        mma_gemm<0><<<dim3(4, 128, 3), 128, SMEM_HI>>>(gq, gk, gv);
    }

    // Windowed attention -> fp16 msg directly into Af (guide no longer needed)
    attn_kernel<<<dim3(32, 32), 256>>>(Q, K, V, Af);

    // M2 = msg @ Wm^T with full hi/lo weight split (output path precision)
    {
        GemmArgs gm = { Af, Whi + 3 * W_ELEMS, Wlo + 3 * W_ELEMS, M2, 128 };
        mma_gemm<1><<<dim3(4, 128, 1), 128, SMEM_LO>>>(gm, gm, gm);
    }

    // LayerNorm + transpose to channel-major output
    ln_kernel<<<1024, 256>>>(M2, gamma, beta, out);
}

// round 12
// speedup vs baseline: 2.0445x; 1.1597x over previous
#include <cuda_runtime.h>
#include <cuda_fp16.h>
#include <cstdint>

#define NPOS 16384   // 128*128 guide positions
#define LPOS 1024    // 32*32 low positions
#define DMODEL 512

// ---------------------------------------------------------------------------
// Scratch (static device globals — no allocation APIs allowed)
// ---------------------------------------------------------------------------
__device__ __half g_Af [NPOS * DMODEL];          // fp16 activations (guide, then msg)
__device__ __half g_Lf [LPOS * DMODEL];          // fp16 low activations
__device__ __half g_Whi[4 * DMODEL * DMODEL];    // weight hi (fp16)
__device__ float g_Q [NPOS * DMODEL];
__device__ float g_K [LPOS * DMODEL];
__device__ float g_V [LPOS * DMODEL];
__device__ float g_M2[NPOS * DMODEL];

// ---------------------------------------------------------------------------
// Baseline-PTX helpers (sm_80+ features only: work on plain sm_103 target)
// ---------------------------------------------------------------------------
__device__ __forceinline__ uint32_t smem_u32(const void* p) {
    uint32_t a;
    asm("{ .reg .u64 t; cvta.to.shared.u64 t, %1; cvt.u32.u64 %0, t; }" : "=r"(a) : "l"(p));
    return a;
}

#define CP16(dst, src) \
    asm volatile("cp.async.cg.shared.global [%0], [%1], 16;" :: "r"(dst), "l"(src))
#define CP_COMMIT() asm volatile("cp.async.commit_group;" ::: "memory")
#define CP_WAIT(n)  asm volatile("cp.async.wait_group %0;" :: "n"(n) : "memory")

#define LDSM4(r0, r1, r2, r3, addr) \
    asm volatile("ldmatrix.sync.aligned.m8n8.x4.shared.b16 {%0,%1,%2,%3}, [%4];" \
        : "=r"(r0), "=r"(r1), "=r"(r2), "=r"(r3) : "r"(addr))

#define MMA16816F(d, a, b) \
    asm volatile("mma.sync.aligned.m16n8k16.row.col.f32.f16.f16.f32 " \
        "{%0,%1,%2,%3}, {%4,%5,%6,%7}, {%8,%9}, {%0,%1,%2,%3};" \
        : "+f"((d)[0]), "+f"((d)[1]), "+f"((d)[2]), "+f"((d)[3]) \
        : "r"((a)[0]), "r"((a)[1]), "r"((a)[2]), "r"((a)[3]), \
          "r"((b)[0]), "r"((b)[1]))

// ---------------------------------------------------------------------------
// mma_gemm: C[m][n] = sum_k A[m][k]*B[n][k], K=512, fp32 out.
// A and B both rounded to fp16 (1 MMA per k16), fp32 accumulate.
// CTA: 128x128 tile, 128 threads = 4 warps (2m x 2n), warp tile 64x64.
// K chunks of 32, 3 smem buffers, single barrier per chunk, 2 CTAs/SM.
// Three independent GEMMs selected by blockIdx.z; CTAs with
// blockIdx.y >= mtiles exit immediately (QKV share one launch).
// ---------------------------------------------------------------------------
#define PITCH 80
#define TILE_B (128 * PITCH)            // 10240 B per operand tile
#define STAGE_B (2 * TILE_B)            // A, Bhi = 20480 B per stage
#define NSTAGE 3

struct GemmArgs {
    const __half* A;
    const __half* Bhi;
    float* C;
    int mtiles;
};

__global__ __launch_bounds__(128, 2)
void mma_gemm(GemmArgs g0, GemmArgs g1, GemmArgs g2)
{
    const GemmArgs& ga_ = (blockIdx.z == 0) ? g0 : (blockIdx.z == 1) ? g1 : g2;
    if ((int)blockIdx.y >= ga_.mtiles) return;

    const __half* __restrict__ A   = ga_.A;
    const __half* __restrict__ Bhi = ga_.Bhi;
    float* __restrict__ C = ga_.C;

    extern __shared__ char smem[];
    const uint32_t sb = smem_u32(smem);

    const int tid  = threadIdx.x;
    const int wid  = tid >> 5;
    const int lane = tid & 31;
    const int bm0  = blockIdx.y * 128;
    const int bn0  = blockIdx.x * 128;
    const int wm   = (wid >> 1) * 64;    // warp m offset in tile
    const int wn   = (wid & 1) * 64;     // warp n offset in tile

    float acc[4][8][4];
#pragma unroll
    for (int i = 0; i < 4; i++)
#pragma unroll
        for (int j = 0; j < 8; j++)
#pragma unroll
            for (int r = 0; r < 4; r++) acc[i][j][r] = 0.f;

    // ---- async stage loader: 8 x 16B per thread per stage
    auto load_stage = [&](int s, int k0) {
        const uint32_t base = sb + s * STAGE_B;
#pragma unroll
        for (int i = 0; i < 4; i++) {
            const int idx = tid + 128 * i;        // 0..511
            const int row = idx >> 2;             // 0..127
            const int c   = idx & 3;              // 16B chunk in 64B row
            const uint32_t off = row * PITCH + c * 16;
            const size_t ga = ((size_t)(bm0 + row) * 512 + k0) * 2 + c * 16;
            const size_t gb = ((size_t)(bn0 + row) * 512 + k0) * 2 + c * 16;
            CP16(base + off,          (const char*)A   + ga);
            CP16(base + TILE_B + off, (const char*)Bhi + gb);
        }
        CP_COMMIT();
    };

    // ---- compute one k32 chunk from stage s
    auto compute_stage = [&](int s) {
        const uint32_t base = sb + s * STAGE_B;
#pragma unroll
        for (int kk = 0; kk < 2; kk++) {          // two k16 halves
            const uint32_t koff = kk * 32;        // byte offset of k16 half

            uint32_t a[4][4];
#pragma unroll
            for (int f = 0; f < 4; f++) {
                const uint32_t ra = base +
                    (uint32_t)(wm + f * 16 + (lane & 15)) * PITCH +
                    koff + ((lane >> 4) << 4);
                LDSM4(a[f][0], a[f][1], a[f][2], a[f][3], ra);
            }

            uint32_t bh[8][2];
#pragma unroll
            for (int g = 0; g < 4; g++) {
                const uint32_t rb = base + TILE_B +
                    (uint32_t)(wn + g * 16 + (lane & 7) + ((lane >> 4) << 3)) * PITCH +
                    koff + (((lane >> 3) & 1) << 4);
                LDSM4(bh[2*g][0], bh[2*g][1], bh[2*g+1][0], bh[2*g+1][1], rb);
            }

#pragma unroll
            for (int f = 0; f < 4; f++)
#pragma unroll
                for (int g = 0; g < 8; g++)
                    MMA16816F(acc[f][g], a[f], bh[g]);
        }
    };

    // ---- prologue: 2 chunks in flight
    load_stage(0, 0);
    load_stage(1, 32);

#pragma unroll
    for (int c = 0; c < 16; c++) {
        if (c < 15) { CP_WAIT(1); } else { CP_WAIT(0); }
        __syncthreads();
        if (c + 2 < 16) load_stage((c + 2) % NSTAGE, (c + 2) * 32);
        compute_stage(c % NSTAGE);
    }

    // ---- epilogue: acc -> C (fp32, row stride 512)
    const int qrow = lane >> 2;          // 0..7
    const int qcol = (lane & 3) * 2;     // 0,2,4,6
#pragma unroll
    for (int f = 0; f < 4; f++)
#pragma unroll
        for (int g = 0; g < 8; g++) {
            const int row = bm0 + wm + f * 16 + qrow;
            const int col = bn0 + wn + g * 8 + qcol;
            *(float2*)(C + (size_t)row * 512 + col) =
                make_float2(acc[f][g][0], acc[f][g][1]);
            *(float2*)(C + (size_t)(row + 8) * 512 + col) =
                make_float2(acc[f][g][2], acc[f][g][3]);
        }
}

// ---------------------------------------------------------------------------
// conv_all: ALL input conversion in one launch. 1-D grid, 256 threads.
//   blocks [0, 8192)     : guide transpose tiles (512 x 16)   fp32->fp16
//   blocks [8192, 8704)  : low transpose tiles   (32 x 16)
//   blocks [8704, 9728)  : weight round          (4 x 256)
// ---------------------------------------------------------------------------
__global__ __launch_bounds__(256)
void conv_all(const float* __restrict__ guide, const float* __restrict__ low,
              const float4* __restrict__ w0, const float4* __restrict__ w1,
              const float4* __restrict__ w2, const float4* __restrict__ w3,
              __half* __restrict__ Af, __half* __restrict__ Lf,
              __half* __restrict__ whi)
{
    const int b = blockIdx.x;
    const int tid = threadIdx.x;

    if (b < 8704) {
        // ---- transpose+convert: channel-major fp32 -> row-major fp16
        const float* in;
        __half* outp;
        int M, mtile, ktile;
        if (b < 8192) { in = guide; outp = Af; M = NPOS; mtile = b & 511; ktile = b >> 9; }
        else { const int id = b - 8192; in = low; outp = Lf; M = LPOS; mtile = id & 31; ktile = id >> 5; }

        __shared__ float t[32][33];
        const int tx = tid & 31, ty = tid >> 5;      // 32 x 8
        const int mb = mtile * 32, kb = ktile * 32;
#pragma unroll
        for (int j = 0; j < 4; j++)
            t[ty + 8 * j][tx] = in[(size_t)(kb + ty + 8 * j) * M + mb + tx];
        __syncthreads();
#pragma unroll
        for (int j = 0; j < 4; j++) {
            const float v = t[tx][ty + 8 * j];
            outp[(size_t)(mb + ty + 8 * j) * 512 + kb + tx] = __float2half(v);
        }
    } else {
        // ---- weights: fp32 -> fp16 (round)
        const int id = b - 8704;                 // 0..1023
        const int z = id >> 8;
        const float4* src = (z == 0) ? w0 : (z == 1) ? w1 : (z == 2) ? w2 : w3;
        const int i = (id & 255) * 256 + tid;    // 0..65535
        const float4 v = src[i];

        const __half hx = __float2half(v.x), hy = __float2half(v.y);
        const __half hz = __float2half(v.z), hw = __float2half(v.w);

        const size_t o = (size_t)z * (DMODEL * DMODEL / 4) + i;
        ((ushort4*)whi)[o] = make_ushort4(__half_as_ushort(hx), __half_as_ushort(hy),
                                          __half_as_ushort(hz), __half_as_ushort(hw));
    }
}

// ---------------------------------------------------------------------------
// Windowed attention, 256 threads: tid = head*32 + half*16 + pos.
// (pos,head) pair splits the 64-elem head dim across two same-warp threads
// (shfl_xor 16 combines score partials); each thread emits 32 out channels.
// One block per 4x4 guide tile (shared 3x3 window). Writes fp16.
// ---------------------------------------------------------------------------
__global__ __launch_bounds__(256)
void attn_kernel(const float* __restrict__ Q, const float* __restrict__ Km,
                 const float* __restrict__ Vm, __half* __restrict__ msg)
{
    __shared__ float Ks[9][512];
    __shared__ float Vs[9][512];

    const int tx = blockIdx.x;
    const int ty = blockIdx.y;
    const int tid = threadIdx.x;

    for (int idx = tid; idx < 9 * 128; idx += 256) {
        const int k  = idx >> 7;
        const int c4 = idx & 127;
        const int yy = min(max(ty - 1 + k / 3, 0), 31);
        const int xx = min(max(tx - 1 + k % 3, 0), 31);
        const int p  = yy * 32 + xx;
        ((float4*)&Ks[k][0])[c4] = ((const float4*)(Km + (size_t)p * 512))[c4];
        ((float4*)&Vs[k][0])[c4] = ((const float4*)(Vm + (size_t)p * 512))[c4];
    }
    __syncthreads();

    const int pos  = tid & 15;           // 0..15
    const int half = (tid >> 4) & 1;     // 0..1
    const int head = tid >> 5;           // 0..7
    const int n = (ty * 4 + (pos >> 2)) * 128 + tx * 4 + (pos & 3);
    const int coff = head * 64 + half * 32;   // this thread's 32 channels

    const float4* q4 = (const float4*)(Q + (size_t)n * 512 + coff);

    float acc[9];
#pragma unroll
    for (int k = 0; k < 9; k++) acc[k] = 0.f;

#pragma unroll
    for (int e = 0; e < 8; e++) {
        float4 qv = q4[e];
#pragma unroll
        for (int k = 0; k < 9; k++) {
            float4 kv = ((const float4*)&Ks[k][coff])[e];
            acc[k] += qv.x * kv.x + qv.y * kv.y + qv.z * kv.z + qv.w * kv.w;
        }
    }
    // combine the two halves (threads tid and tid^16 share a warp)
#pragma unroll
    for (int k = 0; k < 9; k++)
        acc[k] += __shfl_xor_sync(0xffffffffu, acc[k], 16);

    float mx = acc[0];
#pragma unroll
    for (int k = 1; k < 9; k++) mx = fmaxf(mx, acc[k]);
    float s = 0.f;
#pragma unroll
    for (int k = 0; k < 9; k++) { acc[k] = __expf(0.125f * (acc[k] - mx)); s += acc[k]; }
    const float inv = 1.f / s;
#pragma unroll
    for (int k = 0; k < 9; k++) acc[k] *= inv;

    __half* outp = msg + (size_t)n * 512 + coff;
#pragma unroll
    for (int e = 0; e < 8; e++) {
        float4 o = make_float4(0.f, 0.f, 0.f, 0.f);
#pragma unroll
        for (int k = 0; k < 9; k++) {
            float4 vv = ((const float4*)&Vs[k][coff])[e];
            o.x += acc[k] * vv.x;
            o.y += acc[k] * vv.y;
            o.z += acc[k] * vv.z;
            o.w += acc[k] * vv.w;
        }
        const __half2 h0 = __floats2half2_rn(o.x, o.y);
        const __half2 h1 = __floats2half2_rn(o.z, o.w);
        uint2 pk;
        pk.x = *(const uint32_t*)&h0;
        pk.y = *(const uint32_t*)&h1;
        *(uint2*)(outp + e * 4) = pk;
    }
}

// ---------------------------------------------------------------------------
// LayerNorm over d=512 per position + transpose to channel-major output.
// ---------------------------------------------------------------------------
__global__ __launch_bounds__(256)
void ln_kernel(const float* __restrict__ X, const float* __restrict__ gamma,
               const float* __restrict__ beta, float* __restrict__ out)
{
    __shared__ float sm[16 * 513];

    const int nb   = blockIdx.x * 16;
    const int warp = threadIdx.x >> 5;
    const int lane = threadIdx.x & 31;

    for (int r = warp; r < 16; r += 8) {
        const int n = nb + r;
        const float* row = X + (size_t)n * 512;
        float v[16];
        float s = 0.f;
#pragma unroll
        for (int j = 0; j < 16; j++) { v[j] = row[lane + 32 * j]; s += v[j]; }
#pragma unroll
        for (int o = 16; o > 0; o >>= 1) s += __shfl_xor_sync(0xffffffffu, s, o);
        const float mu = s * (1.f / 512.f);
        float q = 0.f;
#pragma unroll
        for (int j = 0; j < 16; j++) { float d = v[j] - mu; q += d * d; }
#pragma unroll
        for (int o = 16; o > 0; o >>= 1) q += __shfl_xor_sync(0xffffffffu, q, o);
        const float rstd = rsqrtf(q * (1.f / 512.f) + 1e-5f);
#pragma unroll
        for (int j = 0; j < 16; j++) {
            const int o = lane + 32 * j;
            sm[r * 513 + o] = (v[j] - mu) * rstd * gamma[o] + beta[o];
        }
    }
    __syncthreads();

    const int i  = threadIdx.x & 15;
    const int ob = threadIdx.x >> 4;
    for (int o = ob; o < 512; o += 16)
        out[(size_t)o * 16384 + nb + i] = sm[i * 513 + o];
}

// ---------------------------------------------------------------------------
extern "C" void kernel_launch(void* const* d_in, const int* in_sizes, int n_in,
                              void* d_out, int out_size)
{
    const float* low   = (const float*)d_in[0];
    const float* guide = (const float*)d_in[1];
    const float* Wq    = (const float*)d_in[2];
    const float* Wk    = (const float*)d_in[3];
    const float* Wv    = (const float*)d_in[4];
    const float* Wm    = (const float*)d_in[5];
    const float* gamma = (const float*)d_in[6];
    const float* beta  = (const float*)d_in[7];
    float* out = (float*)d_out;

    __half *Af, *Lf, *Whi;
    float *Q, *K, *V, *M2;
    cudaGetSymbolAddress((void**)&Af,  g_Af);
    cudaGetSymbolAddress((void**)&Lf,  g_Lf);
    cudaGetSymbolAddress((void**)&Whi, g_Whi);
    cudaGetSymbolAddress((void**)&Q,   g_Q);
    cudaGetSymbolAddress((void**)&K,   g_K);
    cudaGetSymbolAddress((void**)&V,   g_V);
    cudaGetSymbolAddress((void**)&M2,  g_M2);

    const int W_ELEMS = DMODEL * DMODEL;              // 262144
    const int GEMM_SMEM = NSTAGE * STAGE_B;           // 61440

    cudaFuncSetAttribute(mma_gemm, cudaFuncAttributeMaxDynamicSharedMemorySize,
                         GEMM_SMEM);

    // ALL conversions in one launch
    conv_all<<<9728, 256>>>(guide, low,
                            (const float4*)Wq, (const float4*)Wk,
                            (const float4*)Wv, (const float4*)Wm,
                            Af, Lf, Whi);

    // Q, K, V projections in ONE launch (1 MMA per k16)
    {
        GemmArgs gq = { Af, Whi,               Q, 128 };
        GemmArgs gk = { Lf, Whi + 1 * W_ELEMS, K, 8 };
        GemmArgs gv = { Lf, Whi + 2 * W_ELEMS, V, 8 };
        mma_gemm<<<dim3(4, 128, 3), 128, GEMM_SMEM>>>(gq, gk, gv);
    }

    // Windowed attention -> fp16 msg directly into Af (guide no longer needed)
    attn_kernel<<<dim3(32, 32), 256>>>(Q, K, V, Af);

    // M2 = msg @ Wm^T (fp16-rounded Wm, same error scale as QKV path)
    {
        GemmArgs gm = { Af, Whi + 3 * W_ELEMS, M2, 128 };
        mma_gemm<<<dim3(4, 128, 1), 128, GEMM_SMEM>>>(gm, gm, gm);
    }

    // LayerNorm + transpose to channel-major output
    ln_kernel<<<1024, 256>>>(M2, gamma, beta, out);
}

// round 13
// speedup vs baseline: 2.0835x; 1.0191x over previous
#include <cuda_runtime.h>
#include <cuda_fp16.h>
#include <cstdint>

#define NPOS 16384   // 128*128 guide positions
#define LPOS 1024    // 32*32 low positions
#define DMODEL 512

// ---------------------------------------------------------------------------
// Scratch (static device globals — no allocation APIs allowed)
// ---------------------------------------------------------------------------
__device__ __half g_Af [NPOS * DMODEL];          // fp16 activations (guide, then msg)
__device__ __half g_Lf [LPOS * DMODEL];          // fp16 low activations
__device__ __half g_Whi[4 * DMODEL * DMODEL];    // weight hi (fp16)
__device__ __half g_Q [NPOS * DMODEL];           // fp16 Q
__device__ __half g_K [LPOS * DMODEL];           // fp16 K
__device__ __half g_V [LPOS * DMODEL];           // fp16 V
__device__ float  g_M2[NPOS * DMODEL];

// ---------------------------------------------------------------------------
// Baseline-PTX helpers (sm_80+ features only: work on plain sm_103 target)
// ---------------------------------------------------------------------------
__device__ __forceinline__ uint32_t smem_u32(const void* p) {
    uint32_t a;
    asm("{ .reg .u64 t; cvta.to.shared.u64 t, %1; cvt.u32.u64 %0, t; }" : "=r"(a) : "l"(p));
    return a;
}

#define CP16(dst, src) \
    asm volatile("cp.async.cg.shared.global [%0], [%1], 16;" :: "r"(dst), "l"(src))
#define CP_COMMIT() asm volatile("cp.async.commit_group;" ::: "memory")
#define CP_WAIT(n)  asm volatile("cp.async.wait_group %0;" :: "n"(n) : "memory")

#define LDSM4(r0, r1, r2, r3, addr) \
    asm volatile("ldmatrix.sync.aligned.m8n8.x4.shared.b16 {%0,%1,%2,%3}, [%4];" \
        : "=r"(r0), "=r"(r1), "=r"(r2), "=r"(r3) : "r"(addr))

#define MMA16816F(d, a, b) \
    asm volatile("mma.sync.aligned.m16n8k16.row.col.f32.f16.f16.f32 " \
        "{%0,%1,%2,%3}, {%4,%5,%6,%7}, {%8,%9}, {%0,%1,%2,%3};" \
        : "+f"((d)[0]), "+f"((d)[1]), "+f"((d)[2]), "+f"((d)[3]) \
        : "r"((a)[0]), "r"((a)[1]), "r"((a)[2]), "r"((a)[3]), \
          "r"((b)[0]), "r"((b)[1]))

// ---------------------------------------------------------------------------
// mma_gemm<OutT>: C[m][n] = sum_k A[m][k]*B[n][k], K=512.
// A and B rounded to fp16 (1 MMA per k16), fp32 accumulate.
// OutT=float: direct float2 epilogue (M2 path).
// OutT=__half: smem-staged epilogue (pitch-136 tile, then 16B coalesced
//              stores) — rules out narrow/conflicted store patterns.
// CTA: 128x128 tile, 128 threads = 4 warps (2m x 2n), warp tile 64x64.
// K chunks of 32, 3 smem buffers, single barrier per chunk, 2 CTAs/SM.
// Three independent GEMMs selected by blockIdx.z; CTAs with
// blockIdx.y >= mtiles exit immediately (QKV share one launch).
// ---------------------------------------------------------------------------
#define PITCH 80
#define TILE_B (128 * PITCH)            // 10240 B per operand tile
#define STAGE_B (2 * TILE_B)            // A, Bhi = 20480 B per stage
#define NSTAGE 3
#define EPI_PITCH 136                   // halves per staged row (272B, 4-bank skew)

struct GemmArgs {
    const __half* A;
    const __half* Bhi;
    void* C;
    int mtiles;
};

template<typename OutT>
__global__ __launch_bounds__(128, 2)
void mma_gemm(GemmArgs g0, GemmArgs g1, GemmArgs g2)
{
    const GemmArgs& ga_ = (blockIdx.z == 0) ? g0 : (blockIdx.z == 1) ? g1 : g2;
    if ((int)blockIdx.y >= ga_.mtiles) return;

    const __half* __restrict__ A   = ga_.A;
    const __half* __restrict__ Bhi = ga_.Bhi;

    extern __shared__ char smem[];
    const uint32_t sb = smem_u32(smem);

    const int tid  = threadIdx.x;
    const int wid  = tid >> 5;
    const int lane = tid & 31;
    const int bm0  = blockIdx.y * 128;
    const int bn0  = blockIdx.x * 128;
    const int wm   = (wid >> 1) * 64;    // warp m offset in tile
    const int wn   = (wid & 1) * 64;     // warp n offset in tile

    float acc[4][8][4];
#pragma unroll
    for (int i = 0; i < 4; i++)
#pragma unroll
        for (int j = 0; j < 8; j++)
#pragma unroll
            for (int r = 0; r < 4; r++) acc[i][j][r] = 0.f;

    // ---- async stage loader: 8 x 16B per thread per stage
    auto load_stage = [&](int s, int k0) {
        const uint32_t base = sb + s * STAGE_B;
#pragma unroll
        for (int i = 0; i < 4; i++) {
            const int idx = tid + 128 * i;        // 0..511
            const int row = idx >> 2;             // 0..127
            const int c   = idx & 3;              // 16B chunk in 64B row
            const uint32_t off = row * PITCH + c * 16;
            const size_t ga = ((size_t)(bm0 + row) * 512 + k0) * 2 + c * 16;
            const size_t gb = ((size_t)(bn0 + row) * 512 + k0) * 2 + c * 16;
            CP16(base + off,          (const char*)A   + ga);
            CP16(base + TILE_B + off, (const char*)Bhi + gb);
        }
        CP_COMMIT();
    };

    // ---- compute one k32 chunk from stage s
    auto compute_stage = [&](int s) {
        const uint32_t base = sb + s * STAGE_B;
#pragma unroll
        for (int kk = 0; kk < 2; kk++) {          // two k16 halves
            const uint32_t koff = kk * 32;        // byte offset of k16 half

            uint32_t a[4][4];
#pragma unroll
            for (int f = 0; f < 4; f++) {
                const uint32_t ra = base +
                    (uint32_t)(wm + f * 16 + (lane & 15)) * PITCH +
                    koff + ((lane >> 4) << 4);
                LDSM4(a[f][0], a[f][1], a[f][2], a[f][3], ra);
            }

            uint32_t bh[8][2];
#pragma unroll
            for (int g = 0; g < 4; g++) {
                const uint32_t rb = base + TILE_B +
                    (uint32_t)(wn + g * 16 + (lane & 7) + ((lane >> 4) << 3)) * PITCH +
                    koff + (((lane >> 3) & 1) << 4);
                LDSM4(bh[2*g][0], bh[2*g][1], bh[2*g+1][0], bh[2*g+1][1], rb);
            }

#pragma unroll
            for (int f = 0; f < 4; f++)
#pragma unroll
                for (int g = 0; g < 8; g++)
                    MMA16816F(acc[f][g], a[f], bh[g]);
        }
    };

    // ---- prologue: 2 chunks in flight
    load_stage(0, 0);
    load_stage(1, 32);

#pragma unroll
    for (int c = 0; c < 16; c++) {
        if (c < 15) { CP_WAIT(1); } else { CP_WAIT(0); }
        __syncthreads();
        if (c + 2 < 16) load_stage((c + 2) % NSTAGE, (c + 2) * 32);
        compute_stage(c % NSTAGE);
    }

    const int qrow = lane >> 2;          // 0..7
    const int qcol = (lane & 3) * 2;     // 0,2,4,6

    if (sizeof(OutT) == 4) {
        // ---- fp32 epilogue: direct float2 stores
        float* C = (float*)ga_.C;
#pragma unroll
        for (int f = 0; f < 4; f++)
#pragma unroll
            for (int g = 0; g < 8; g++) {
                const int row = bm0 + wm + f * 16 + qrow;
                const int col = bn0 + wn + g * 8 + qcol;
                *(float2*)(C + (size_t)row * 512 + col) =
                    make_float2(acc[f][g][0], acc[f][g][1]);
                *(float2*)(C + (size_t)(row + 8) * 512 + col) =
                    make_float2(acc[f][g][2], acc[f][g][3]);
            }
    } else {
        // ---- fp16 epilogue: stage in smem (pitch 136), coalesced 16B stores
        __half* C = (__half*)ga_.C;
        __syncthreads();                 // stage buffers dead; reuse smem
        __half* st = (__half*)smem;
#pragma unroll
        for (int f = 0; f < 4; f++)
#pragma unroll
            for (int g = 0; g < 8; g++) {
                const int r0 = wm + f * 16 + qrow;
                const int c0 = wn + g * 8 + qcol;
                *(__half2*)(st + r0 * EPI_PITCH + c0) =
                    __floats2half2_rn(acc[f][g][0], acc[f][g][1]);
                *(__half2*)(st + (r0 + 8) * EPI_PITCH + c0) =
                    __floats2half2_rn(acc[f][g][2], acc[f][g][3]);
            }
        __syncthreads();
#pragma unroll
        for (int i = 0; i < 16; i++) {
            const int idx = tid + 128 * i;       // 0..2047 (128 rows x 16 chunks)
            const int r = idx >> 4;
            const int c = idx & 15;
            *(uint4*)((char*)(C + (size_t)(bm0 + r) * 512 + bn0) + c * 16) =
                *(const uint4*)((const char*)(st + r * EPI_PITCH) + c * 16);
        }
    }
}

// ---------------------------------------------------------------------------
// conv_all: ALL input conversion in one launch. 1-D grid, 256 threads.
//   blocks [0, 8192)     : guide transpose tiles (512 x 16)   fp32->fp16
//   blocks [8192, 8704)  : low transpose tiles   (32 x 16)
//   blocks [8704, 9728)  : weight round          (4 x 256)
// ---------------------------------------------------------------------------
__global__ __launch_bounds__(256)
void conv_all(const float* __restrict__ guide, const float* __restrict__ low,
              const float4* __restrict__ w0, const float4* __restrict__ w1,
              const float4* __restrict__ w2, const float4* __restrict__ w3,
              __half* __restrict__ Af, __half* __restrict__ Lf,
              __half* __restrict__ whi)
{
    const int b = blockIdx.x;
    const int tid = threadIdx.x;

    if (b < 8704) {
        const float* in;
        __half* outp;
        int M, mtile, ktile;
        if (b < 8192) { in = guide; outp = Af; M = NPOS; mtile = b & 511; ktile = b >> 9; }
        else { const int id = b - 8192; in = low; outp = Lf; M = LPOS; mtile = id & 31; ktile = id >> 5; }

        __shared__ float t[32][33];
        const int tx = tid & 31, ty = tid >> 5;      // 32 x 8
        const int mb = mtile * 32, kb = ktile * 32;
#pragma unroll
        for (int j = 0; j < 4; j++)
            t[ty + 8 * j][tx] = in[(size_t)(kb + ty + 8 * j) * M + mb + tx];
        __syncthreads();
#pragma unroll
        for (int j = 0; j < 4; j++) {
            const float v = t[tx][ty + 8 * j];
            outp[(size_t)(mb + ty + 8 * j) * 512 + kb + tx] = __float2half(v);
        }
    } else {
        const int id = b - 8704;                 // 0..1023
        const int z = id >> 8;
        const float4* src = (z == 0) ? w0 : (z == 1) ? w1 : (z == 2) ? w2 : w3;
        const int i = (id & 255) * 256 + tid;    // 0..65535
        const float4 v = src[i];

        const __half hx = __float2half(v.x), hy = __float2half(v.y);
        const __half hz = __float2half(v.z), hw = __float2half(v.w);

        const size_t o = (size_t)z * (DMODEL * DMODEL / 4) + i;
        ((ushort4*)whi)[o] = make_ushort4(__half_as_ushort(hx), __half_as_ushort(hy),
                                          __half_as_ushort(hz), __half_as_ushort(hw));
    }
}

// ---------------------------------------------------------------------------
// Windowed attention, 256 threads: tid = head*32 + half*16 + pos.
// Q/K/V fp16; K/V converted to fp32 at smem staging, Q via half2 loads.
// All arithmetic fp32. One block per 4x4 guide tile. Writes fp16 msg.
// ---------------------------------------------------------------------------
__global__ __launch_bounds__(256)
void attn_kernel(const __half* __restrict__ Q, const __half* __restrict__ Km,
                 const __half* __restrict__ Vm, __half* __restrict__ msg)
{
    __shared__ float Ks[9][512];
    __shared__ float Vs[9][512];

    const int tx = blockIdx.x;
    const int ty = blockIdx.y;
    const int tid = threadIdx.x;

    for (int idx = tid; idx < 9 * 128; idx += 256) {
        const int k  = idx >> 7;
        const int c4 = idx & 127;          // 4-elem slot
        const int yy = min(max(ty - 1 + k / 3, 0), 31);
        const int xx = min(max(tx - 1 + k % 3, 0), 31);
        const int p  = yy * 32 + xx;
        const __half2* ks = (const __half2*)(Km + (size_t)p * 512) + c4 * 2;
        const __half2* vs = (const __half2*)(Vm + (size_t)p * 512) + c4 * 2;
        const float2 k0 = __half22float2(ks[0]);
        const float2 k1 = __half22float2(ks[1]);
        const float2 v0 = __half22float2(vs[0]);
        const float2 v1 = __half22float2(vs[1]);
        ((float4*)&Ks[k][0])[c4] = make_float4(k0.x, k0.y, k1.x, k1.y);
        ((float4*)&Vs[k][0])[c4] = make_float4(v0.x, v0.y, v1.x, v1.y);
    }
    __syncthreads();

    const int pos  = tid & 15;           // 0..15
    const int half = (tid >> 4) & 1;     // 0..1
    const int head = tid >> 5;           // 0..7
    const int n = (ty * 4 + (pos >> 2)) * 128 + tx * 4 + (pos & 3);
    const int coff = head * 64 + half * 32;   // this thread's 32 channels

    const __half2* q2 = (const __half2*)(Q + (size_t)n * 512 + coff);

    float acc[9];
#pragma unroll
    for (int k = 0; k < 9; k++) acc[k] = 0.f;

#pragma unroll
    for (int e = 0; e < 8; e++) {
        const float2 qa = __half22float2(q2[2 * e]);
        const float2 qb = __half22float2(q2[2 * e + 1]);
#pragma unroll
        for (int k = 0; k < 9; k++) {
            float4 kv = ((const float4*)&Ks[k][coff])[e];
            acc[k] += qa.x * kv.x + qa.y * kv.y + qb.x * kv.z + qb.y * kv.w;
        }
    }
    // combine the two halves (threads tid and tid^16 share a warp)
#pragma unroll
    for (int k = 0; k < 9; k++)
        acc[k] += __shfl_xor_sync(0xffffffffu, acc[k], 16);

    float mx = acc[0];
#pragma unroll
    for (int k = 1; k < 9; k++) mx = fmaxf(mx, acc[k]);
    float s = 0.f;
#pragma unroll
    for (int k = 0; k < 9; k++) { acc[k] = __expf(0.125f * (acc[k] - mx)); s += acc[k]; }
    const float inv = 1.f / s;
#pragma unroll
    for (int k = 0; k < 9; k++) acc[k] *= inv;

    __half* outp = msg + (size_t)n * 512 + coff;
#pragma unroll
    for (int e = 0; e < 8; e++) {
        float4 o = make_float4(0.f, 0.f, 0.f, 0.f);
#pragma unroll
        for (int k = 0; k < 9; k++) {
            float4 vv = ((const float4*)&Vs[k][coff])[e];
            o.x += acc[k] * vv.x;
            o.y += acc[k] * vv.y;
            o.z += acc[k] * vv.z;
            o.w += acc[k] * vv.w;
        }
        const __half2 h0 = __floats2half2_rn(o.x, o.y);
        const __half2 h1 = __floats2half2_rn(o.z, o.w);
        uint2 pk;
        pk.x = *(const uint32_t*)&h0;
        pk.y = *(const uint32_t*)&h1;
        *(uint2*)(outp + e * 4) = pk;
    }
}

// ---------------------------------------------------------------------------
// LayerNorm over d=512 per position + transpose to channel-major output.
// ---------------------------------------------------------------------------
__global__ __launch_bounds__(256)
void ln_kernel(const float* __restrict__ X, const float* __restrict__ gamma,
               const float* __restrict__ beta, float* __restrict__ out)
{
    __shared__ float sm[16 * 513];

    const int nb   = blockIdx.x * 16;
    const int warp = threadIdx.x >> 5;
    const int lane = threadIdx.x & 31;

    for (int r = warp; r < 16; r += 8) {
        const int n = nb + r;
        const float* row = X + (size_t)n * 512;
        float v[16];
        float s = 0.f;
#pragma unroll
        for (int j = 0; j < 16; j++) { v[j] = row[lane + 32 * j]; s += v[j]; }
#pragma unroll
        for (int o = 16; o > 0; o >>= 1) s += __shfl_xor_sync(0xffffffffu, s, o);
        const float mu = s * (1.f / 512.f);
        float q = 0.f;
#pragma unroll
        for (int j = 0; j < 16; j++) { float d = v[j] - mu; q += d * d; }
#pragma unroll
        for (int o = 16; o > 0; o >>= 1) q += __shfl_xor_sync(0xffffffffu, q, o);
        const float rstd = rsqrtf(q * (1.f / 512.f) + 1e-5f);
#pragma unroll
        for (int j = 0; j < 16; j++) {
            const int o = lane + 32 * j;
            sm[r * 513 + o] = (v[j] - mu) * rstd * gamma[o] + beta[o];
        }
    }
    __syncthreads();

    const int i  = threadIdx.x & 15;
    const int ob = threadIdx.x >> 4;
    for (int o = ob; o < 512; o += 16)
        out[(size_t)o * 16384 + nb + i] = sm[i * 513 + o];
}

// ---------------------------------------------------------------------------
extern "C" void kernel_launch(void* const* d_in, const int* in_sizes, int n_in,
                              void* d_out, int out_size)
{
    const float* low   = (const float*)d_in[0];
    const float* guide = (const float*)d_in[1];
    const float* Wq    = (const float*)d_in[2];
    const float* Wk    = (const float*)d_in[3];
    const float* Wv    = (const float*)d_in[4];
    const float* Wm    = (const float*)d_in[5];
    const float* gamma = (const float*)d_in[6];
    const float* beta  = (const float*)d_in[7];
    float* out = (float*)d_out;

    __half *Af, *Lf, *Whi, *Q, *K, *V;
    float *M2;
    cudaGetSymbolAddress((void**)&Af,  g_Af);
    cudaGetSymbolAddress((void**)&Lf,  g_Lf);
    cudaGetSymbolAddress((void**)&Whi, g_Whi);
    cudaGetSymbolAddress((void**)&Q,   g_Q);
    cudaGetSymbolAddress((void**)&K,   g_K);
    cudaGetSymbolAddress((void**)&V,   g_V);
    cudaGetSymbolAddress((void**)&M2,  g_M2);

    const int W_ELEMS = DMODEL * DMODEL;              // 262144
    const int GEMM_SMEM = NSTAGE * STAGE_B;           // 61440

    cudaFuncSetAttribute(mma_gemm<__half>, cudaFuncAttributeMaxDynamicSharedMemorySize,
                         GEMM_SMEM);
    cudaFuncSetAttribute(mma_gemm<float>, cudaFuncAttributeMaxDynamicSharedMemorySize,
                         GEMM_SMEM);

    // ALL conversions in one launch
    conv_all<<<9728, 256>>>(guide, low,
                            (const float4*)Wq, (const float4*)Wk,
                            (const float4*)Wv, (const float4*)Wm,
                            Af, Lf, Whi);

    // Q, K, V projections in ONE launch (1 MMA per k16), fp16 outputs
    {
        GemmArgs gq = { Af, Whi,               Q, 128 };
        GemmArgs gk = { Lf, Whi + 1 * W_ELEMS, K, 8 };
        GemmArgs gv = { Lf, Whi + 2 * W_ELEMS, V, 8 };
        mma_gemm<__half><<<dim3(4, 128, 3), 128, GEMM_SMEM>>>(gq, gk, gv);
    }

    // Windowed attention -> fp16 msg directly into Af (guide no longer needed)
    attn_kernel<<<dim3(32, 32), 256>>>(Q, K, V, Af);

    // M2 = msg @ Wm^T (fp32 out for LayerNorm)
    {
        GemmArgs gm = { Af, Whi + 3 * W_ELEMS, M2, 128 };
        mma_gemm<float><<<dim3(4, 128, 1), 128, GEMM_SMEM>>>(gm, gm, gm);
    }

    // LayerNorm + transpose to channel-major output
    ln_kernel<<<1024, 256>>>(M2, gamma, beta, out);
}

// round 14
// speedup vs baseline: 2.1159x; 1.0155x over previous
#include <cuda_runtime.h>
#include <cuda_fp16.h>
#include <cstdint>

#define NPOS 16384   // 128*128 guide positions
#define LPOS 1024    // 32*32 low positions
#define DMODEL 512

// ---------------------------------------------------------------------------
// Scratch (static device globals — no allocation APIs allowed)
// ---------------------------------------------------------------------------
__device__ __half g_Af [NPOS * DMODEL];          // fp16 activations (guide, then msg)
__device__ __half g_Lf [LPOS * DMODEL];          // fp16 low activations
__device__ __half g_Whi[4 * DMODEL * DMODEL];    // weight hi (fp16)
__device__ __half g_Q [NPOS * DMODEL];           // fp16 Q, then fp16 M2
__device__ __half g_K [LPOS * DMODEL];           // fp16 K
__device__ __half g_V [LPOS * DMODEL];           // fp16 V

// ---------------------------------------------------------------------------
// Baseline-PTX helpers (sm_80+ features only: work on plain sm_103 target)
// ---------------------------------------------------------------------------
__device__ __forceinline__ uint32_t smem_u32(const void* p) {
    uint32_t a;
    asm("{ .reg .u64 t; cvta.to.shared.u64 t, %1; cvt.u32.u64 %0, t; }" : "=r"(a) : "l"(p));
    return a;
}

#define CP16(dst, src) \
    asm volatile("cp.async.cg.shared.global [%0], [%1], 16;" :: "r"(dst), "l"(src))
#define CP_COMMIT() asm volatile("cp.async.commit_group;" ::: "memory")
#define CP_WAIT(n)  asm volatile("cp.async.wait_group %0;" :: "n"(n) : "memory")

#define LDSM4(r0, r1, r2, r3, addr) \
    asm volatile("ldmatrix.sync.aligned.m8n8.x4.shared.b16 {%0,%1,%2,%3}, [%4];" \
        : "=r"(r0), "=r"(r1), "=r"(r2), "=r"(r3) : "r"(addr))

#define MMA16816F(d, a, b) \
    asm volatile("mma.sync.aligned.m16n8k16.row.col.f32.f16.f16.f32 " \
        "{%0,%1,%2,%3}, {%4,%5,%6,%7}, {%8,%9}, {%0,%1,%2,%3};" \
        : "+f"((d)[0]), "+f"((d)[1]), "+f"((d)[2]), "+f"((d)[3]) \
        : "r"((a)[0]), "r"((a)[1]), "r"((a)[2]), "r"((a)[3]), \
          "r"((b)[0]), "r"((b)[1]))

// ---------------------------------------------------------------------------
// mma_gemm: C[m][n] = sum_k A[m][k]*B[n][k], K=512, fp16 out.
// A and B rounded to fp16 (1 MMA per k16), fp32 accumulate.
// fp16 epilogue: smem-staged (pitch-136 tile) then 16B coalesced stores.
// CTA: 128x128 tile, 128 threads = 4 warps (2m x 2n), warp tile 64x64.
// K chunks of 32, 3 smem buffers, single barrier per chunk, 2 CTAs/SM.
// Three independent GEMMs selected by blockIdx.z; CTAs with
// blockIdx.y >= mtiles exit immediately (QKV share one launch).
// ---------------------------------------------------------------------------
#define PITCH 80
#define TILE_B (128 * PITCH)            // 10240 B per operand tile
#define STAGE_B (2 * TILE_B)            // A, Bhi = 20480 B per stage
#define NSTAGE 3
#define EPI_PITCH 136                   // halves per staged row (272B, 4-bank skew)

struct GemmArgs {
    const __half* A;
    const __half* Bhi;
    __half* C;
    int mtiles;
};

__global__ __launch_bounds__(128, 2)
void mma_gemm(GemmArgs g0, GemmArgs g1, GemmArgs g2)
{
    const GemmArgs& ga_ = (blockIdx.z == 0) ? g0 : (blockIdx.z == 1) ? g1 : g2;
    if ((int)blockIdx.y >= ga_.mtiles) return;

    const __half* __restrict__ A   = ga_.A;
    const __half* __restrict__ Bhi = ga_.Bhi;

    extern __shared__ char smem[];
    const uint32_t sb = smem_u32(smem);

    const int tid  = threadIdx.x;
    const int wid  = tid >> 5;
    const int lane = tid & 31;
    const int bm0  = blockIdx.y * 128;
    const int bn0  = blockIdx.x * 128;
    const int wm   = (wid >> 1) * 64;    // warp m offset in tile
    const int wn   = (wid & 1) * 64;     // warp n offset in tile

    float acc[4][8][4];
#pragma unroll
    for (int i = 0; i < 4; i++)
#pragma unroll
        for (int j = 0; j < 8; j++)
#pragma unroll
            for (int r = 0; r < 4; r++) acc[i][j][r] = 0.f;

    // ---- async stage loader: 8 x 16B per thread per stage
    auto load_stage = [&](int s, int k0) {
        const uint32_t base = sb + s * STAGE_B;
#pragma unroll
        for (int i = 0; i < 4; i++) {
            const int idx = tid + 128 * i;        // 0..511
            const int row = idx >> 2;             // 0..127
            const int c   = idx & 3;              // 16B chunk in 64B row
            const uint32_t off = row * PITCH + c * 16;
            const size_t ga = ((size_t)(bm0 + row) * 512 + k0) * 2 + c * 16;
            const size_t gb = ((size_t)(bn0 + row) * 512 + k0) * 2 + c * 16;
            CP16(base + off,          (const char*)A   + ga);
            CP16(base + TILE_B + off, (const char*)Bhi + gb);
        }
        CP_COMMIT();
    };

    // ---- compute one k32 chunk from stage s
    auto compute_stage = [&](int s) {
        const uint32_t base = sb + s * STAGE_B;
#pragma unroll
        for (int kk = 0; kk < 2; kk++) {          // two k16 halves
            const uint32_t koff = kk * 32;        // byte offset of k16 half

            uint32_t a[4][4];
#pragma unroll
            for (int f = 0; f < 4; f++) {
                const uint32_t ra = base +
                    (uint32_t)(wm + f * 16 + (lane & 15)) * PITCH +
                    koff + ((lane >> 4) << 4);
                LDSM4(a[f][0], a[f][1], a[f][2], a[f][3], ra);
            }

            uint32_t bh[8][2];
#pragma unroll
            for (int g = 0; g < 4; g++) {
                const uint32_t rb = base + TILE_B +
                    (uint32_t)(wn + g * 16 + (lane & 7) + ((lane >> 4) << 3)) * PITCH +
                    koff + (((lane >> 3) & 1) << 4);
                LDSM4(bh[2*g][0], bh[2*g][1], bh[2*g+1][0], bh[2*g+1][1], rb);
            }

#pragma unroll
            for (int f = 0; f < 4; f++)
#pragma unroll
                for (int g = 0; g < 8; g++)
                    MMA16816F(acc[f][g], a[f], bh[g]);
        }
    };

    // ---- prologue: 2 chunks in flight
    load_stage(0, 0);
    load_stage(1, 32);

#pragma unroll
    for (int c = 0; c < 16; c++) {
        if (c < 15) { CP_WAIT(1); } else { CP_WAIT(0); }
        __syncthreads();
        if (c + 2 < 16) load_stage((c + 2) % NSTAGE, (c + 2) * 32);
        compute_stage(c % NSTAGE);
    }

    // ---- fp16 epilogue: stage in smem (pitch 136), coalesced 16B stores
    const int qrow = lane >> 2;          // 0..7
    const int qcol = (lane & 3) * 2;     // 0,2,4,6
    __half* C = ga_.C;
    __syncthreads();                     // stage buffers dead; reuse smem
    __half* st = (__half*)smem;
#pragma unroll
    for (int f = 0; f < 4; f++)
#pragma unroll
        for (int g = 0; g < 8; g++) {
            const int r0 = wm + f * 16 + qrow;
            const int c0 = wn + g * 8 + qcol;
            *(__half2*)(st + r0 * EPI_PITCH + c0) =
                __floats2half2_rn(acc[f][g][0], acc[f][g][1]);
            *(__half2*)(st + (r0 + 8) * EPI_PITCH + c0) =
                __floats2half2_rn(acc[f][g][2], acc[f][g][3]);
        }
    __syncthreads();
#pragma unroll
    for (int i = 0; i < 16; i++) {
        const int idx = tid + 128 * i;       // 0..2047 (128 rows x 16 chunks)
        const int r = idx >> 4;
        const int c = idx & 15;
        *(uint4*)((char*)(C + (size_t)(bm0 + r) * 512 + bn0) + c * 16) =
            *(const uint4*)((const char*)(st + r * EPI_PITCH) + c * 16);
    }
}

// ---------------------------------------------------------------------------
// conv_all: ALL input conversion in one launch. 1-D grid, 256 threads.
//   blocks [0, 8192)     : guide transpose tiles (512 x 16)   fp32->fp16
//   blocks [8192, 8704)  : low transpose tiles   (32 x 16)
//   blocks [8704, 9728)  : weight round          (4 x 256)
// ---------------------------------------------------------------------------
__global__ __launch_bounds__(256)
void conv_all(const float* __restrict__ guide, const float* __restrict__ low,
              const float4* __restrict__ w0, const float4* __restrict__ w1,
              const float4* __restrict__ w2, const float4* __restrict__ w3,
              __half* __restrict__ Af, __half* __restrict__ Lf,
              __half* __restrict__ whi)
{
    const int b = blockIdx.x;
    const int tid = threadIdx.x;

    if (b < 8704) {
        const float* in;
        __half* outp;
        int M, mtile, ktile;
        if (b < 8192) { in = guide; outp = Af; M = NPOS; mtile = b & 511; ktile = b >> 9; }
        else { const int id = b - 8192; in = low; outp = Lf; M = LPOS; mtile = id & 31; ktile = id >> 5; }

        __shared__ float t[32][33];
        const int tx = tid & 31, ty = tid >> 5;      // 32 x 8
        const int mb = mtile * 32, kb = ktile * 32;
#pragma unroll
        for (int j = 0; j < 4; j++)
            t[ty + 8 * j][tx] = in[(size_t)(kb + ty + 8 * j) * M + mb + tx];
        __syncthreads();
#pragma unroll
        for (int j = 0; j < 4; j++) {
            const float v = t[tx][ty + 8 * j];
            outp[(size_t)(mb + ty + 8 * j) * 512 + kb + tx] = __float2half(v);
        }
    } else {
        const int id = b - 8704;                 // 0..1023
        const int z = id >> 8;
        const float4* src = (z == 0) ? w0 : (z == 1) ? w1 : (z == 2) ? w2 : w3;
        const int i = (id & 255) * 256 + tid;    // 0..65535
        const float4 v = src[i];

        const __half hx = __float2half(v.x), hy = __float2half(v.y);
        const __half hz = __float2half(v.z), hw = __float2half(v.w);

        const size_t o = (size_t)z * (DMODEL * DMODEL / 4) + i;
        ((ushort4*)whi)[o] = make_ushort4(__half_as_ushort(hx), __half_as_ushort(hy),
                                          __half_as_ushort(hz), __half_as_ushort(hw));
    }
}

// ---------------------------------------------------------------------------
// Windowed attention, 256 threads: tid = head*32 + half*16 + pos.
// Q/K/V fp16; K/V converted to fp32 at smem staging, Q via half2 loads.
// All arithmetic fp32. One block per 4x4 guide tile. Writes fp16 msg.
// ---------------------------------------------------------------------------
__global__ __launch_bounds__(256)
void attn_kernel(const __half* __restrict__ Q, const __half* __restrict__ Km,
                 const __half* __restrict__ Vm, __half* __restrict__ msg)
{
    __shared__ float Ks[9][512];
    __shared__ float Vs[9][512];

    const int tx = blockIdx.x;
    const int ty = blockIdx.y;
    const int tid = threadIdx.x;

    for (int idx = tid; idx < 9 * 128; idx += 256) {
        const int k  = idx >> 7;
        const int c4 = idx & 127;          // 4-elem slot
        const int yy = min(max(ty - 1 + k / 3, 0), 31);
        const int xx = min(max(tx - 1 + k % 3, 0), 31);
        const int p  = yy * 32 + xx;
        const __half2* ks = (const __half2*)(Km + (size_t)p * 512) + c4 * 2;
        const __half2* vs = (const __half2*)(Vm + (size_t)p * 512) + c4 * 2;
        const float2 k0 = __half22float2(ks[0]);
        const float2 k1 = __half22float2(ks[1]);
        const float2 v0 = __half22float2(vs[0]);
        const float2 v1 = __half22float2(vs[1]);
        ((float4*)&Ks[k][0])[c4] = make_float4(k0.x, k0.y, k1.x, k1.y);
        ((float4*)&Vs[k][0])[c4] = make_float4(v0.x, v0.y, v1.x, v1.y);
    }
    __syncthreads();

    const int pos  = tid & 15;           // 0..15
    const int half = (tid >> 4) & 1;     // 0..1
    const int head = tid >> 5;           // 0..7
    const int n = (ty * 4 + (pos >> 2)) * 128 + tx * 4 + (pos & 3);
    const int coff = head * 64 + half * 32;   // this thread's 32 channels

    const __half2* q2 = (const __half2*)(Q + (size_t)n * 512 + coff);

    float acc[9];
#pragma unroll
    for (int k = 0; k < 9; k++) acc[k] = 0.f;

#pragma unroll
    for (int e = 0; e < 8; e++) {
        const float2 qa = __half22float2(q2[2 * e]);
        const float2 qb = __half22float2(q2[2 * e + 1]);
#pragma unroll
        for (int k = 0; k < 9; k++) {
            float4 kv = ((const float4*)&Ks[k][coff])[e];
            acc[k] += qa.x * kv.x + qa.y * kv.y + qb.x * kv.z + qb.y * kv.w;
        }
    }
    // combine the two halves (threads tid and tid^16 share a warp)
#pragma unroll
    for (int k = 0; k < 9; k++)
        acc[k] += __shfl_xor_sync(0xffffffffu, acc[k], 16);

    float mx = acc[0];
#pragma unroll
    for (int k = 1; k < 9; k++) mx = fmaxf(mx, acc[k]);
    float s = 0.f;
#pragma unroll
    for (int k = 0; k < 9; k++) { acc[k] = __expf(0.125f * (acc[k] - mx)); s += acc[k]; }
    const float inv = 1.f / s;
#pragma unroll
    for (int k = 0; k < 9; k++) acc[k] *= inv;

    __half* outp = msg + (size_t)n * 512 + coff;
#pragma unroll
    for (int e = 0; e < 8; e++) {
        float4 o = make_float4(0.f, 0.f, 0.f, 0.f);
#pragma unroll
        for (int k = 0; k < 9; k++) {
            float4 vv = ((const float4*)&Vs[k][coff])[e];
            o.x += acc[k] * vv.x;
            o.y += acc[k] * vv.y;
            o.z += acc[k] * vv.z;
            o.w += acc[k] * vv.w;
        }
        const __half2 h0 = __floats2half2_rn(o.x, o.y);
        const __half2 h1 = __floats2half2_rn(o.z, o.w);
        uint2 pk;
        pk.x = *(const uint32_t*)&h0;
        pk.y = *(const uint32_t*)&h1;
        *(uint2*)(outp + e * 4) = pk;
    }
}

// ---------------------------------------------------------------------------
// LayerNorm over d=512 per position (fp16 input, fp32 math) + transpose to
// channel-major fp32 output.
// ---------------------------------------------------------------------------
__global__ __launch_bounds__(256)
void ln_kernel(const __half* __restrict__ X, const float* __restrict__ gamma,
               const float* __restrict__ beta, float* __restrict__ out)
{
    __shared__ float sm[16 * 513];

    const int nb   = blockIdx.x * 16;
    const int warp = threadIdx.x >> 5;
    const int lane = threadIdx.x & 31;

    for (int r = warp; r < 16; r += 8) {
        const int n = nb + r;
        const __half* row = X + (size_t)n * 512;
        float v[16];
        float s = 0.f;
#pragma unroll
        for (int j = 0; j < 16; j++) { v[j] = __half2float(row[lane + 32 * j]); s += v[j]; }
#pragma unroll
        for (int o = 16; o > 0; o >>= 1) s += __shfl_xor_sync(0xffffffffu, s, o);
        const float mu = s * (1.f / 512.f);
        float q = 0.f;
#pragma unroll
        for (int j = 0; j < 16; j++) { float d = v[j] - mu; q += d * d; }
#pragma unroll
        for (int o = 16; o > 0; o >>= 1) q += __shfl_xor_sync(0xffffffffu, q, o);
        const float rstd = rsqrtf(q * (1.f / 512.f) + 1e-5f);
#pragma unroll
        for (int j = 0; j < 16; j++) {
            const int o = lane + 32 * j;
            sm[r * 513 + o] = (v[j] - mu) * rstd * gamma[o] + beta[o];
        }
    }
    __syncthreads();

    const int i  = threadIdx.x & 15;
    const int ob = threadIdx.x >> 4;
    for (int o = ob; o < 512; o += 16)
        out[(size_t)o * 16384 + nb + i] = sm[i * 513 + o];
}

// ---------------------------------------------------------------------------
extern "C" void kernel_launch(void* const* d_in, const int* in_sizes, int n_in,
                              void* d_out, int out_size)
{
    const float* low   = (const float*)d_in[0];
    const float* guide = (const float*)d_in[1];
    const float* Wq    = (const float*)d_in[2];
    const float* Wk    = (const float*)d_in[3];
    const float* Wv    = (const float*)d_in[4];
    const float* Wm    = (const float*)d_in[5];
    const float* gamma = (const float*)d_in[6];
    const float* beta  = (const float*)d_in[7];
    float* out = (float*)d_out;

    __half *Af, *Lf, *Whi, *Q, *K, *V;
    cudaGetSymbolAddress((void**)&Af,  g_Af);
    cudaGetSymbolAddress((void**)&Lf,  g_Lf);
    cudaGetSymbolAddress((void**)&Whi, g_Whi);
    cudaGetSymbolAddress((void**)&Q,   g_Q);
    cudaGetSymbolAddress((void**)&K,   g_K);
    cudaGetSymbolAddress((void**)&V,   g_V);

    const int W_ELEMS = DMODEL * DMODEL;              // 262144
    const int GEMM_SMEM = NSTAGE * STAGE_B;           // 61440

    cudaFuncSetAttribute(mma_gemm, cudaFuncAttributeMaxDynamicSharedMemorySize,
                         GEMM_SMEM);

    // ALL conversions in one launch
    conv_all<<<9728, 256>>>(guide, low,
                            (const float4*)Wq, (const float4*)Wk,
                            (const float4*)Wv, (const float4*)Wm,
                            Af, Lf, Whi);

    // Q, K, V projections in ONE launch (1 MMA per k16), fp16 outputs
    {
        GemmArgs gq = { Af, Whi,               Q, 128 };
        GemmArgs gk = { Lf, Whi + 1 * W_ELEMS, K, 8 };
        GemmArgs gv = { Lf, Whi + 2 * W_ELEMS, V, 8 };
        mma_gemm<<<dim3(4, 128, 3), 128, GEMM_SMEM>>>(gq, gk, gv);
    }

    // Windowed attention -> fp16 msg directly into Af (guide no longer needed)
    attn_kernel<<<dim3(32, 32), 256>>>(Q, K, V, Af);

    // M2 = msg @ Wm^T, fp16 out into g_Q (Q is dead after attn)
    {
        GemmArgs gm = { Af, Whi + 3 * W_ELEMS, Q, 128 };
        mma_gemm<<<dim3(4, 128, 1), 128, GEMM_SMEM>>>(gm, gm, gm);
    }

    // LayerNorm (fp16 in, fp32 math) + transpose to channel-major output
    ln_kernel<<<1024, 256>>>(Q, gamma, beta, out);
}

// round 15
// speedup vs baseline: 2.1289x; 1.0061x over previous
#include <cuda_runtime.h>
#include <cuda_fp16.h>
#include <cstdint>

#define NPOS 16384   // 128*128 guide positions
#define LPOS 1024    // 32*32 low positions
#define DMODEL 512

// ---------------------------------------------------------------------------
// Scratch (static device globals — no allocation APIs allowed)
// ---------------------------------------------------------------------------
__device__ __half g_Af [NPOS * DMODEL];          // fp16 activations (guide, then msg)
__device__ __half g_Lf [LPOS * DMODEL];          // fp16 low activations
__device__ __half g_Whi[4 * DMODEL * DMODEL];    // weight hi (fp16)
__device__ __half g_Q [NPOS * DMODEL];           // fp16 Q, then fp16 M2
__device__ __half g_K [LPOS * DMODEL];           // fp16 K
__device__ __half g_V [LPOS * DMODEL];           // fp16 V

// ---------------------------------------------------------------------------
// Baseline-PTX helpers (sm_80+ features only: work on plain sm_103 target)
// ---------------------------------------------------------------------------
__device__ __forceinline__ uint32_t smem_u32(const void* p) {
    uint32_t a;
    asm("{ .reg .u64 t; cvta.to.shared.u64 t, %1; cvt.u32.u64 %0, t; }" : "=r"(a) : "l"(p));
    return a;
}

#define CP16(dst, src) \
    asm volatile("cp.async.cg.shared.global [%0], [%1], 16;" :: "r"(dst), "l"(src))
#define CP_COMMIT() asm volatile("cp.async.commit_group;" ::: "memory")
#define CP_WAIT(n)  asm volatile("cp.async.wait_group %0;" :: "n"(n) : "memory")

#define LDSM4(r0, r1, r2, r3, addr) \
    asm volatile("ldmatrix.sync.aligned.m8n8.x4.shared.b16 {%0,%1,%2,%3}, [%4];" \
        : "=r"(r0), "=r"(r1), "=r"(r2), "=r"(r3) : "r"(addr))

#define MMA16816F(d, a, b) \
    asm volatile("mma.sync.aligned.m16n8k16.row.col.f32.f16.f16.f32 " \
        "{%0,%1,%2,%3}, {%4,%5,%6,%7}, {%8,%9}, {%0,%1,%2,%3};" \
        : "+f"((d)[0]), "+f"((d)[1]), "+f"((d)[2]), "+f"((d)[3]) \
        : "r"((a)[0]), "r"((a)[1]), "r"((a)[2]), "r"((a)[3]), \
          "r"((b)[0]), "r"((b)[1]))

// ---------------------------------------------------------------------------
// mma_gemm: C[m][n] = sum_k A[m][k]*B[n][k], K=512, fp16 out.
// A and B rounded to fp16 (1 MMA per k16), fp32 accumulate.
// fp16 epilogue: smem-staged (pitch-136 tile) then 16B coalesced stores.
// CTA: 128x128 tile, 128 threads = 4 warps (2m x 2n), warp tile 64x64.
// K chunks of 32, 3 smem buffers, single barrier per chunk, 2 CTAs/SM.
// Three independent GEMMs selected by blockIdx.z; CTAs with
// blockIdx.y >= mtiles exit immediately (QKV share one launch).
// ---------------------------------------------------------------------------
#define PITCH 80
#define TILE_B (128 * PITCH)            // 10240 B per operand tile
#define STAGE_B (2 * TILE_B)            // A, Bhi = 20480 B per stage
#define NSTAGE 3
#define EPI_PITCH 136                   // halves per staged row (272B, 4-bank skew)

struct GemmArgs {
    const __half* A;
    const __half* Bhi;
    __half* C;
    int mtiles;
};

__global__ __launch_bounds__(128, 2)
void mma_gemm(GemmArgs g0, GemmArgs g1, GemmArgs g2)
{
    const GemmArgs& ga_ = (blockIdx.z == 0) ? g0 : (blockIdx.z == 1) ? g1 : g2;
    if ((int)blockIdx.y >= ga_.mtiles) return;

    const __half* __restrict__ A   = ga_.A;
    const __half* __restrict__ Bhi = ga_.Bhi;

    extern __shared__ char smem[];
    const uint32_t sb = smem_u32(smem);

    const int tid  = threadIdx.x;
    const int wid  = tid >> 5;
    const int lane = tid & 31;
    const int bm0  = blockIdx.y * 128;
    const int bn0  = blockIdx.x * 128;
    const int wm   = (wid >> 1) * 64;    // warp m offset in tile
    const int wn   = (wid & 1) * 64;     // warp n offset in tile

    float acc[4][8][4];
#pragma unroll
    for (int i = 0; i < 4; i++)
#pragma unroll
        for (int j = 0; j < 8; j++)
#pragma unroll
            for (int r = 0; r < 4; r++) acc[i][j][r] = 0.f;

    // ---- async stage loader: 8 x 16B per thread per stage
    auto load_stage = [&](int s, int k0) {
        const uint32_t base = sb + s * STAGE_B;
#pragma unroll
        for (int i = 0; i < 4; i++) {
            const int idx = tid + 128 * i;        // 0..511
            const int row = idx >> 2;             // 0..127
            const int c   = idx & 3;              // 16B chunk in 64B row
            const uint32_t off = row * PITCH + c * 16;
            const size_t ga = ((size_t)(bm0 + row) * 512 + k0) * 2 + c * 16;
            const size_t gb = ((size_t)(bn0 + row) * 512 + k0) * 2 + c * 16;
            CP16(base + off,          (const char*)A   + ga);
            CP16(base + TILE_B + off, (const char*)Bhi + gb);
        }
        CP_COMMIT();
    };

    // ---- compute one k32 chunk from stage s
    auto compute_stage = [&](int s) {
        const uint32_t base = sb + s * STAGE_B;
#pragma unroll
        for (int kk = 0; kk < 2; kk++) {          // two k16 halves
            const uint32_t koff = kk * 32;        // byte offset of k16 half

            uint32_t a[4][4];
#pragma unroll
            for (int f = 0; f < 4; f++) {
                const uint32_t ra = base +
                    (uint32_t)(wm + f * 16 + (lane & 15)) * PITCH +
                    koff + ((lane >> 4) << 4);
                LDSM4(a[f][0], a[f][1], a[f][2], a[f][3], ra);
            }

            uint32_t bh[8][2];
#pragma unroll
            for (int g = 0; g < 4; g++) {
                const uint32_t rb = base + TILE_B +
                    (uint32_t)(wn + g * 16 + (lane & 7) + ((lane >> 4) << 3)) * PITCH +
                    koff + (((lane >> 3) & 1) << 4);
                LDSM4(bh[2*g][0], bh[2*g][1], bh[2*g+1][0], bh[2*g+1][1], rb);
            }

#pragma unroll
            for (int f = 0; f < 4; f++)
#pragma unroll
                for (int g = 0; g < 8; g++)
                    MMA16816F(acc[f][g], a[f], bh[g]);
        }
    };

    // ---- prologue: 2 chunks in flight
    load_stage(0, 0);
    load_stage(1, 32);

#pragma unroll
    for (int c = 0; c < 16; c++) {
        if (c < 15) { CP_WAIT(1); } else { CP_WAIT(0); }
        __syncthreads();
        if (c + 2 < 16) load_stage((c + 2) % NSTAGE, (c + 2) * 32);
        compute_stage(c % NSTAGE);
    }

    // ---- fp16 epilogue: stage in smem (pitch 136), coalesced 16B stores
    const int qrow = lane >> 2;          // 0..7
    const int qcol = (lane & 3) * 2;     // 0,2,4,6
    __half* C = ga_.C;
    __syncthreads();                     // stage buffers dead; reuse smem
    __half* st = (__half*)smem;
#pragma unroll
    for (int f = 0; f < 4; f++)
#pragma unroll
        for (int g = 0; g < 8; g++) {
            const int r0 = wm + f * 16 + qrow;
            const int c0 = wn + g * 8 + qcol;
            *(__half2*)(st + r0 * EPI_PITCH + c0) =
                __floats2half2_rn(acc[f][g][0], acc[f][g][1]);
            *(__half2*)(st + (r0 + 8) * EPI_PITCH + c0) =
                __floats2half2_rn(acc[f][g][2], acc[f][g][3]);
        }
    __syncthreads();
#pragma unroll
    for (int i = 0; i < 16; i++) {
        const int idx = tid + 128 * i;       // 0..2047 (128 rows x 16 chunks)
        const int r = idx >> 4;
        const int c = idx & 15;
        *(uint4*)((char*)(C + (size_t)(bm0 + r) * 512 + bn0) + c * 16) =
            *(const uint4*)((const char*)(st + r * EPI_PITCH) + c * 16);
    }
}

// ---------------------------------------------------------------------------
// conv_all: ALL input conversion in one launch. 1-D grid, 256 threads.
// Transpose tiles are 64k x 32m so the fp16 writes are half2 per thread,
// 128B-contiguous per warp (full-sector stores).
//   blocks [0, 4096)     : guide transpose tiles (512 m x 8 k)
//   blocks [4096, 4352)  : low transpose tiles   (32 m x 8 k)
//   blocks [4352, 5376)  : weight round          (4 x 256)
// ---------------------------------------------------------------------------
__global__ __launch_bounds__(256)
void conv_all(const float* __restrict__ guide, const float* __restrict__ low,
              const float4* __restrict__ w0, const float4* __restrict__ w1,
              const float4* __restrict__ w2, const float4* __restrict__ w3,
              __half* __restrict__ Af, __half* __restrict__ Lf,
              __half* __restrict__ whi)
{
    const int b = blockIdx.x;
    const int tid = threadIdx.x;

    if (b < 4352) {
        const float* in;
        __half* outp;
        int M, mtile, ktile;
        if (b < 4096) { in = guide; outp = Af; M = NPOS; mtile = b & 511; ktile = b >> 9; }
        else { const int id = b - 4096; in = low; outp = Lf; M = LPOS; mtile = id & 31; ktile = id >> 5; }

        __shared__ float t[64][33];
        const int mb = mtile * 32, kb = ktile * 64;

        // load 64 k-rows x 32 m floats (coalesced 128B per 8 lanes/row)
#pragma unroll
        for (int q = 0; q < 2; q++) {
            const int fid = tid + 256 * q;       // 0..511
            const int kr  = fid >> 3;            // 0..63
            const int c4  = fid & 7;             // m-chunk of 4
            const float4 v = *(const float4*)(in + (size_t)(kb + kr) * M + mb + c4 * 4);
            t[kr][c4 * 4 + 0] = v.x;
            t[kr][c4 * 4 + 1] = v.y;
            t[kr][c4 * 4 + 2] = v.z;
            t[kr][c4 * 4 + 3] = v.w;
        }
        __syncthreads();

        // store 32 m-rows x 64 k halves (half2 per thread, 128B per warp)
#pragma unroll
        for (int q = 0; q < 4; q++) {
            const int i  = tid + 256 * q;        // 0..1023
            const int m  = i >> 5;               // 0..31
            const int kh = i & 31;               // k-pair 0..31
            const __half2 h = __floats2half2_rn(t[2 * kh][m], t[2 * kh + 1][m]);
            *(__half2*)(outp + (size_t)(mb + m) * 512 + kb + 2 * kh) = h;
        }
    } else {
        const int id = b - 4352;                 // 0..1023
        const int z = id >> 8;
        const float4* src = (z == 0) ? w0 : (z == 1) ? w1 : (z == 2) ? w2 : w3;
        const int i = (id & 255) * 256 + tid;    // 0..65535
        const float4 v = src[i];

        const __half hx = __float2half(v.x), hy = __float2half(v.y);
        const __half hz = __float2half(v.z), hw = __float2half(v.w);

        const size_t o = (size_t)z * (DMODEL * DMODEL / 4) + i;
        ((ushort4*)whi)[o] = make_ushort4(__half_as_ushort(hx), __half_as_ushort(hy),
                                          __half_as_ushort(hz), __half_as_ushort(hw));
    }
}

// ---------------------------------------------------------------------------
// Windowed attention, 256 threads: tid = head*32 + half*16 + pos.
// Q/K/V fp16; K/V converted to fp32 at smem staging, Q via half2 loads.
// All arithmetic fp32. One block per 4x4 guide tile. Writes fp16 msg.
// ---------------------------------------------------------------------------
__global__ __launch_bounds__(256)
void attn_kernel(const __half* __restrict__ Q, const __half* __restrict__ Km,
                 const __half* __restrict__ Vm, __half* __restrict__ msg)
{
    __shared__ float Ks[9][512];
    __shared__ float Vs[9][512];

    const int tx = blockIdx.x;
    const int ty = blockIdx.y;
    const int tid = threadIdx.x;

    for (int idx = tid; idx < 9 * 128; idx += 256) {
        const int k  = idx >> 7;
        const int c4 = idx & 127;          // 4-elem slot
        const int yy = min(max(ty - 1 + k / 3, 0), 31);
        const int xx = min(max(tx - 1 + k % 3, 0), 31);
        const int p  = yy * 32 + xx;
        const __half2* ks = (const __half2*)(Km + (size_t)p * 512) + c4 * 2;
        const __half2* vs = (const __half2*)(Vm + (size_t)p * 512) + c4 * 2;
        const float2 k0 = __half22float2(ks[0]);
        const float2 k1 = __half22float2(ks[1]);
        const float2 v0 = __half22float2(vs[0]);
        const float2 v1 = __half22float2(vs[1]);
        ((float4*)&Ks[k][0])[c4] = make_float4(k0.x, k0.y, k1.x, k1.y);
        ((float4*)&Vs[k][0])[c4] = make_float4(v0.x, v0.y, v1.x, v1.y);
    }
    __syncthreads();

    const int pos  = tid & 15;           // 0..15
    const int half = (tid >> 4) & 1;     // 0..1
    const int head = tid >> 5;           // 0..7
    const int n = (ty * 4 + (pos >> 2)) * 128 + tx * 4 + (pos & 3);
    const int coff = head * 64 + half * 32;   // this thread's 32 channels

    const __half2* q2 = (const __half2*)(Q + (size_t)n * 512 + coff);

    float acc[9];
#pragma unroll
    for (int k = 0; k < 9; k++) acc[k] = 0.f;

#pragma unroll
    for (int e = 0; e < 8; e++) {
        const float2 qa = __half22float2(q2[2 * e]);
        const float2 qb = __half22float2(q2[2 * e + 1]);
#pragma unroll
        for (int k = 0; k < 9; k++) {
            float4 kv = ((const float4*)&Ks[k][coff])[e];
            acc[k] += qa.x * kv.x + qa.y * kv.y + qb.x * kv.z + qb.y * kv.w;
        }
    }
    // combine the two halves (threads tid and tid^16 share a warp)
#pragma unroll
    for (int k = 0; k < 9; k++)
        acc[k] += __shfl_xor_sync(0xffffffffu, acc[k], 16);

    float mx = acc[0];
#pragma unroll
    for (int k = 1; k < 9; k++) mx = fmaxf(mx, acc[k]);
    float s = 0.f;
#pragma unroll
    for (int k = 0; k < 9; k++) { acc[k] = __expf(0.125f * (acc[k] - mx)); s += acc[k]; }
    const float inv = 1.f / s;
#pragma unroll
    for (int k = 0; k < 9; k++) acc[k] *= inv;

    __half* outp = msg + (size_t)n * 512 + coff;
#pragma unroll
    for (int e = 0; e < 8; e++) {
        float4 o = make_float4(0.f, 0.f, 0.f, 0.f);
#pragma unroll
        for (int k = 0; k < 9; k++) {
            float4 vv = ((const float4*)&Vs[k][coff])[e];
            o.x += acc[k] * vv.x;
            o.y += acc[k] * vv.y;
            o.z += acc[k] * vv.z;
            o.w += acc[k] * vv.w;
        }
        const __half2 h0 = __floats2half2_rn(o.x, o.y);
        const __half2 h1 = __floats2half2_rn(o.z, o.w);
        uint2 pk;
        pk.x = *(const uint32_t*)&h0;
        pk.y = *(const uint32_t*)&h1;
        *(uint2*)(outp + e * 4) = pk;
    }
}

// ---------------------------------------------------------------------------
// LayerNorm over d=512 per position (fp16 input, fp32 math) + transpose to
// channel-major fp32 output. 32 positions per block so output warps write
// 32 consecutive positions (128B full-sector stores). Dynamic smem 66KB,
// pitch 517 (conflict-free transpose reads).
// ---------------------------------------------------------------------------
#define LN_PITCH 517
#define LN_SMEM  (32 * LN_PITCH * 4)     // 66176 B

__global__ __launch_bounds__(256)
void ln_kernel(const __half* __restrict__ X, const float* __restrict__ gamma,
               const float* __restrict__ beta, float* __restrict__ out)
{
    extern __shared__ float sm[];

    const int nb   = blockIdx.x * 32;
    const int warp = threadIdx.x >> 5;
    const int lane = threadIdx.x & 31;

    for (int r = warp; r < 32; r += 8) {
        const int n = nb + r;
        const __half* row = X + (size_t)n * 512;
        float v[16];
        float s = 0.f;
#pragma unroll
        for (int j = 0; j < 16; j++) { v[j] = __half2float(row[lane + 32 * j]); s += v[j]; }
#pragma unroll
        for (int o = 16; o > 0; o >>= 1) s += __shfl_xor_sync(0xffffffffu, s, o);
        const float mu = s * (1.f / 512.f);
        float q = 0.f;
#pragma unroll
        for (int j = 0; j < 16; j++) { float d = v[j] - mu; q += d * d; }
#pragma unroll
        for (int o = 16; o > 0; o >>= 1) q += __shfl_xor_sync(0xffffffffu, q, o);
        const float rstd = rsqrtf(q * (1.f / 512.f) + 1e-5f);
#pragma unroll
        for (int j = 0; j < 16; j++) {
            const int o = lane + 32 * j;
            sm[r * LN_PITCH + o] = (v[j] - mu) * rstd * gamma[o] + beta[o];
        }
    }
    __syncthreads();

    // transposed store: warp ob writes channels ob, ob+8, ... for 32 positions
    const int i  = threadIdx.x & 31;     // position within the 32
    const int ob = threadIdx.x >> 5;     // 0..7
    for (int o = ob; o < 512; o += 8)
        out[(size_t)o * 16384 + nb + i] = sm[i * LN_PITCH + o];
}

// ---------------------------------------------------------------------------
extern "C" void kernel_launch(void* const* d_in, const int* in_sizes, int n_in,
                              void* d_out, int out_size)
{
    const float* low   = (const float*)d_in[0];
    const float* guide = (const float*)d_in[1];
    const float* Wq    = (const float*)d_in[2];
    const float* Wk    = (const float*)d_in[3];
    const float* Wv    = (const float*)d_in[4];
    const float* Wm    = (const float*)d_in[5];
    const float* gamma = (const float*)d_in[6];
    const float* beta  = (const float*)d_in[7];
    float* out = (float*)d_out;

    __half *Af, *Lf, *Whi, *Q, *K, *V;
    cudaGetSymbolAddress((void**)&Af,  g_Af);
    cudaGetSymbolAddress((void**)&Lf,  g_Lf);
    cudaGetSymbolAddress((void**)&Whi, g_Whi);
    cudaGetSymbolAddress((void**)&Q,   g_Q);
    cudaGetSymbolAddress((void**)&K,   g_K);
    cudaGetSymbolAddress((void**)&V,   g_V);

    const int W_ELEMS = DMODEL * DMODEL;              // 262144
    const int GEMM_SMEM = NSTAGE * STAGE_B;           // 61440

    cudaFuncSetAttribute(mma_gemm, cudaFuncAttributeMaxDynamicSharedMemorySize,
                         GEMM_SMEM);
    cudaFuncSetAttribute(ln_kernel, cudaFuncAttributeMaxDynamicSharedMemorySize,
                         LN_SMEM);

    // ALL conversions in one launch
    conv_all<<<5376, 256>>>(guide, low,
                            (const float4*)Wq, (const float4*)Wk,
                            (const float4*)Wv, (const float4*)Wm,
                            Af, Lf, Whi);

    // Q, K, V projections in ONE launch (1 MMA per k16), fp16 outputs
    {
        GemmArgs gq = { Af, Whi,               Q, 128 };
        GemmArgs gk = { Lf, Whi + 1 * W_ELEMS, K, 8 };
        GemmArgs gv = { Lf, Whi + 2 * W_ELEMS, V, 8 };
        mma_gemm<<<dim3(4, 128, 3), 128, GEMM_SMEM>>>(gq, gk, gv);
    }

    // Windowed attention -> fp16 msg directly into Af (guide no longer needed)
    attn_kernel<<<dim3(32, 32), 256>>>(Q, K, V, Af);

    // M2 = msg @ Wm^T, fp16 out into g_Q (Q is dead after attn)
    {
        GemmArgs gm = { Af, Whi + 3 * W_ELEMS, Q, 128 };
        mma_gemm<<<dim3(4, 128, 1), 128, GEMM_SMEM>>>(gm, gm, gm);
    }

    // LayerNorm (fp16 in, fp32 math, 32 pos/block) + channel-major output
    ln_kernel<<<512, 256, LN_SMEM>>>(Q, gamma, beta, out);
}

// round 16
// speedup vs baseline: 2.2837x; 1.0727x over previous
#include <cuda_runtime.h>
#include <cuda_fp16.h>
#include <cstdint>

#define NPOS 16384   // 128*128 guide positions
#define LPOS 1024    // 32*32 low positions
#define DMODEL 512

// ---------------------------------------------------------------------------
// Scratch (static device globals — no allocation APIs allowed)
// ---------------------------------------------------------------------------
__device__ __half g_Af [NPOS * DMODEL];          // fp16 activations (guide, then msg)
__device__ __half g_Lf [LPOS * DMODEL];          // fp16 low activations
__device__ __half g_Whi[4 * DMODEL * DMODEL];    // weight hi (fp16)
__device__ __half g_Q [NPOS * DMODEL];           // fp16 Q, then fp16 M2
__device__ __half g_K [LPOS * DMODEL];           // fp16 K
__device__ __half g_V [LPOS * DMODEL];           // fp16 V

// ---------------------------------------------------------------------------
// Baseline-PTX helpers (sm_80+ features only: work on plain sm_103 target)
// ---------------------------------------------------------------------------
__device__ __forceinline__ uint32_t smem_u32(const void* p) {
    uint32_t a;
    asm("{ .reg .u64 t; cvta.to.shared.u64 t, %1; cvt.u32.u64 %0, t; }" : "=r"(a) : "l"(p));
    return a;
}

#define CP16(dst, src) \
    asm volatile("cp.async.cg.shared.global [%0], [%1], 16;" :: "r"(dst), "l"(src))
#define CP_COMMIT() asm volatile("cp.async.commit_group;" ::: "memory")
#define CP_WAIT(n)  asm volatile("cp.async.wait_group %0;" :: "n"(n) : "memory")

#define LDSM4(r0, r1, r2, r3, addr) \
    asm volatile("ldmatrix.sync.aligned.m8n8.x4.shared.b16 {%0,%1,%2,%3}, [%4];" \
        : "=r"(r0), "=r"(r1), "=r"(r2), "=r"(r3) : "r"(addr))

#define MMA16816F(d, a, b) \
    asm volatile("mma.sync.aligned.m16n8k16.row.col.f32.f16.f16.f32 " \
        "{%0,%1,%2,%3}, {%4,%5,%6,%7}, {%8,%9}, {%0,%1,%2,%3};" \
        : "+f"((d)[0]), "+f"((d)[1]), "+f"((d)[2]), "+f"((d)[3]) \
        : "r"((a)[0]), "r"((a)[1]), "r"((a)[2]), "r"((a)[3]), \
          "r"((b)[0]), "r"((b)[1]))

// ---------------------------------------------------------------------------
// mma_gemm: C[m][n] = sum_k A[m][k]*B[n][k], K=512, fp16 out.
// A and B rounded to fp16 (1 MMA per k16), fp32 accumulate.
// CTA: 128x128 tile, 128 threads = 4 warps (2m x 2n), warp tile 64x64.
// K chunks of 64 (4 k16 per chunk), 2 smem stages, one barrier per chunk:
// half the barrier count of the k32 version, double the MMA burst length,
// so the ~2K-cycle per-iteration overhead is paid 8x instead of 16x.
// Pitch 144B (128B data + 16B skew) keeps LDSM conflict-free.
// Three independent GEMMs selected by blockIdx.z; CTAs with
// blockIdx.y >= mtiles exit immediately (QKV share one launch).
// ---------------------------------------------------------------------------
#define PITCH 144
#define TILE_B (128 * PITCH)            // 18432 B per operand tile
#define STAGE_B (2 * TILE_B)            // A, Bhi = 36864 B per stage
#define NSTAGE 2
#define EPI_PITCH 136                   // halves per staged row (272B, 4-bank skew)

struct GemmArgs {
    const __half* A;
    const __half* Bhi;
    __half* C;
    int mtiles;
};

__global__ __launch_bounds__(128, 2)
void mma_gemm(GemmArgs g0, GemmArgs g1, GemmArgs g2)
{
    const GemmArgs& ga_ = (blockIdx.z == 0) ? g0 : (blockIdx.z == 1) ? g1 : g2;
    if ((int)blockIdx.y >= ga_.mtiles) return;

    const __half* __restrict__ A   = ga_.A;
    const __half* __restrict__ Bhi = ga_.Bhi;

    extern __shared__ char smem[];
    const uint32_t sb = smem_u32(smem);

    const int tid  = threadIdx.x;
    const int wid  = tid >> 5;
    const int lane = tid & 31;
    const int bm0  = blockIdx.y * 128;
    const int bn0  = blockIdx.x * 128;
    const int wm   = (wid >> 1) * 64;    // warp m offset in tile
    const int wn   = (wid & 1) * 64;     // warp n offset in tile

    float acc[4][8][4];
#pragma unroll
    for (int i = 0; i < 4; i++)
#pragma unroll
        for (int j = 0; j < 8; j++)
#pragma unroll
            for (int r = 0; r < 4; r++) acc[i][j][r] = 0.f;

    // ---- async stage loader: 16 x 16B per thread per stage (k64 chunk)
    auto load_stage = [&](int s, int k0) {
        const uint32_t base = sb + s * STAGE_B;
#pragma unroll
        for (int i = 0; i < 8; i++) {
            const int idx = tid + 128 * i;        // 0..1023
            const int row = idx >> 3;             // 0..127
            const int c   = idx & 7;              // 16B chunk in 128B row
            const uint32_t off = row * PITCH + c * 16;
            const size_t ga = ((size_t)(bm0 + row) * 512 + k0) * 2 + c * 16;
            const size_t gb = ((size_t)(bn0 + row) * 512 + k0) * 2 + c * 16;
            CP16(base + off,          (const char*)A   + ga);
            CP16(base + TILE_B + off, (const char*)Bhi + gb);
        }
        CP_COMMIT();
    };

    // ---- compute one k64 chunk from stage s (4 k16 steps)
    auto compute_stage = [&](int s) {
        const uint32_t base = sb + s * STAGE_B;
#pragma unroll
        for (int kk = 0; kk < 4; kk++) {
            const uint32_t koff = kk * 32;        // byte offset of k16 step

            uint32_t a[4][4];
#pragma unroll
            for (int f = 0; f < 4; f++) {
                const uint32_t ra = base +
                    (uint32_t)(wm + f * 16 + (lane & 15)) * PITCH +
                    koff + ((lane >> 4) << 4);
                LDSM4(a[f][0], a[f][1], a[f][2], a[f][3], ra);
            }

            uint32_t bh[8][2];
#pragma unroll
            for (int g = 0; g < 4; g++) {
                const uint32_t rb = base + TILE_B +
                    (uint32_t)(wn + g * 16 + (lane & 7) + ((lane >> 4) << 3)) * PITCH +
                    koff + (((lane >> 3) & 1) << 4);
                LDSM4(bh[2*g][0], bh[2*g][1], bh[2*g+1][0], bh[2*g+1][1], rb);
            }

#pragma unroll
            for (int f = 0; f < 4; f++)
#pragma unroll
                for (int g = 0; g < 8; g++)
                    MMA16816F(acc[f][g], a[f], bh[g]);
        }
    };

    // ---- 2-stage pipeline over 8 k64 chunks
    load_stage(0, 0);

#pragma unroll
    for (int c = 0; c < 8; c++) {
        CP_WAIT(0);
        __syncthreads();
        if (c + 1 < 8) load_stage((c + 1) & 1, (c + 1) * 64);
        compute_stage(c & 1);
    }

    // ---- fp16 epilogue: stage in smem (pitch 136), coalesced 16B stores
    const int qrow = lane >> 2;          // 0..7
    const int qcol = (lane & 3) * 2;     // 0,2,4,6
    __half* C = ga_.C;
    __syncthreads();                     // stage buffers dead; reuse smem
    __half* st = (__half*)smem;
#pragma unroll
    for (int f = 0; f < 4; f++)
#pragma unroll
        for (int g = 0; g < 8; g++) {
            const int r0 = wm + f * 16 + qrow;
            const int c0 = wn + g * 8 + qcol;
            *(__half2*)(st + r0 * EPI_PITCH + c0) =
                __floats2half2_rn(acc[f][g][0], acc[f][g][1]);
            *(__half2*)(st + (r0 + 8) * EPI_PITCH + c0) =
                __floats2half2_rn(acc[f][g][2], acc[f][g][3]);
        }
    __syncthreads();
#pragma unroll
    for (int i = 0; i < 16; i++) {
        const int idx = tid + 128 * i;       // 0..2047 (128 rows x 16 chunks)
        const int r = idx >> 4;
        const int c = idx & 15;
        *(uint4*)((char*)(C + (size_t)(bm0 + r) * 512 + bn0) + c * 16) =
            *(const uint4*)((const char*)(st + r * EPI_PITCH) + c * 16);
    }
}

// ---------------------------------------------------------------------------
// conv_all: ALL input conversion in one launch. 1-D grid, 256 threads.
// Transpose tiles are 64k x 32m so the fp16 writes are half2 per thread,
// 128B-contiguous per warp (full-sector stores).
//   blocks [0, 4096)     : guide transpose tiles (512 m x 8 k)
//   blocks [4096, 4352)  : low transpose tiles   (32 m x 8 k)
//   blocks [4352, 5376)  : weight round          (4 x 256)
// ---------------------------------------------------------------------------
__global__ __launch_bounds__(256)
void conv_all(const float* __restrict__ guide, const float* __restrict__ low,
              const float4* __restrict__ w0, const float4* __restrict__ w1,
              const float4* __restrict__ w2, const float4* __restrict__ w3,
              __half* __restrict__ Af, __half* __restrict__ Lf,
              __half* __restrict__ whi)
{
    const int b = blockIdx.x;
    const int tid = threadIdx.x;

    if (b < 4352) {
        const float* in;
        __half* outp;
        int M, mtile, ktile;
        if (b < 4096) { in = guide; outp = Af; M = NPOS; mtile = b & 511; ktile = b >> 9; }
        else { const int id = b - 4096; in = low; outp = Lf; M = LPOS; mtile = id & 31; ktile = id >> 5; }

        __shared__ float t[64][33];
        const int mb = mtile * 32, kb = ktile * 64;

#pragma unroll
        for (int q = 0; q < 2; q++) {
            const int fid = tid + 256 * q;       // 0..511
            const int kr  = fid >> 3;            // 0..63
            const int c4  = fid & 7;             // m-chunk of 4
            const float4 v = *(const float4*)(in + (size_t)(kb + kr) * M + mb + c4 * 4);
            t[kr][c4 * 4 + 0] = v.x;
            t[kr][c4 * 4 + 1] = v.y;
            t[kr][c4 * 4 + 2] = v.z;
            t[kr][c4 * 4 + 3] = v.w;
        }
        __syncthreads();

#pragma unroll
        for (int q = 0; q < 4; q++) {
            const int i  = tid + 256 * q;        // 0..1023
            const int m  = i >> 5;               // 0..31
            const int kh = i & 31;               // k-pair 0..31
            const __half2 h = __floats2half2_rn(t[2 * kh][m], t[2 * kh + 1][m]);
            *(__half2*)(outp + (size_t)(mb + m) * 512 + kb + 2 * kh) = h;
        }
    } else {
        const int id = b - 4352;                 // 0..1023
        const int z = id >> 8;
        const float4* src = (z == 0) ? w0 : (z == 1) ? w1 : (z == 2) ? w2 : w3;
        const int i = (id & 255) * 256 + tid;    // 0..65535
        const float4 v = src[i];

        const __half hx = __float2half(v.x), hy = __float2half(v.y);
        const __half hz = __float2half(v.z), hw = __float2half(v.w);

        const size_t o = (size_t)z * (DMODEL * DMODEL / 4) + i;
        ((ushort4*)whi)[o] = make_ushort4(__half_as_ushort(hx), __half_as_ushort(hy),
                                          __half_as_ushort(hz), __half_as_ushort(hw));
    }
}

// ---------------------------------------------------------------------------
// Windowed attention, 256 threads: tid = head*32 + half*16 + pos.
// K/V staged in smem as raw fp16 (16B copies, 18.5KB total) and converted in
// registers at use — same op order as before (bit-identical), half the smem.
// One block per 4x4 guide tile. Writes fp16 msg.
// ---------------------------------------------------------------------------
__global__ __launch_bounds__(256)
void attn_kernel(const __half* __restrict__ Q, const __half* __restrict__ Km,
                 const __half* __restrict__ Vm, __half* __restrict__ msg)
{
    __shared__ __half Ks[9][512];
    __shared__ __half Vs[9][512];

    const int tx = blockIdx.x;
    const int ty = blockIdx.y;
    const int tid = threadIdx.x;

    // stage 9 K + 9 V rows as raw bytes: 9 x 64 uint4 each
    for (int idx = tid; idx < 9 * 64; idx += 256) {
        const int k = idx >> 6;
        const int c = idx & 63;            // uint4 slot (8 halves)
        const int yy = min(max(ty - 1 + k / 3, 0), 31);
        const int xx = min(max(tx - 1 + k % 3, 0), 31);
        const int p  = yy * 32 + xx;
        ((uint4*)&Ks[k][0])[c] = ((const uint4*)(Km + (size_t)p * 512))[c];
        ((uint4*)&Vs[k][0])[c] = ((const uint4*)(Vm + (size_t)p * 512))[c];
    }
    __syncthreads();

    const int pos  = tid & 15;           // 0..15
    const int half = (tid >> 4) & 1;     // 0..1
    const int head = tid >> 5;           // 0..7
    const int n = (ty * 4 + (pos >> 2)) * 128 + tx * 4 + (pos & 3);
    const int coff = head * 64 + half * 32;   // this thread's 32 channels

    const __half2* q2 = (const __half2*)(Q + (size_t)n * 512 + coff);

    float acc[9];
#pragma unroll
    for (int k = 0; k < 9; k++) acc[k] = 0.f;

#pragma unroll
    for (int e = 0; e < 8; e++) {
        const float2 qa = __half22float2(q2[2 * e]);
        const float2 qb = __half22float2(q2[2 * e + 1]);
#pragma unroll
        for (int k = 0; k < 9; k++) {
            const __half2* ks2 = (const __half2*)&Ks[k][coff];
            const float2 ka = __half22float2(ks2[2 * e]);
            const float2 kb = __half22float2(ks2[2 * e + 1]);
            acc[k] += qa.x * ka.x + qa.y * ka.y + qb.x * kb.x + qb.y * kb.y;
        }
    }
    // combine the two halves (threads tid and tid^16 share a warp)
#pragma unroll
    for (int k = 0; k < 9; k++)
        acc[k] += __shfl_xor_sync(0xffffffffu, acc[k], 16);

    float mx = acc[0];
#pragma unroll
    for (int k = 1; k < 9; k++) mx = fmaxf(mx, acc[k]);
    float s = 0.f;
#pragma unroll
    for (int k = 0; k < 9; k++) { acc[k] = __expf(0.125f * (acc[k] - mx)); s += acc[k]; }
    const float inv = 1.f / s;
#pragma unroll
    for (int k = 0; k < 9; k++) acc[k] *= inv;

    __half* outp = msg + (size_t)n * 512 + coff;
#pragma unroll
    for (int e = 0; e < 8; e++) {
        float4 o = make_float4(0.f, 0.f, 0.f, 0.f);
#pragma unroll
        for (int k = 0; k < 9; k++) {
            const __half2* vs2 = (const __half2*)&Vs[k][coff];
            const float2 va = __half22float2(vs2[2 * e]);
            const float2 vb = __half22float2(vs2[2 * e + 1]);
            o.x += acc[k] * va.x;
            o.y += acc[k] * va.y;
            o.z += acc[k] * vb.x;
            o.w += acc[k] * vb.y;
        }
        const __half2 h0 = __floats2half2_rn(o.x, o.y);
        const __half2 h1 = __floats2half2_rn(o.z, o.w);
        uint2 pk;
        pk.x = *(const uint32_t*)&h0;
        pk.y = *(const uint32_t*)&h1;
        *(uint2*)(outp + e * 4) = pk;
    }
}

// ---------------------------------------------------------------------------
// LayerNorm over d=512 per position (fp16 input, fp32 math) + transpose to
// channel-major fp32 output. 32 positions per block; output warps write
// 32 consecutive positions (128B full-sector stores). Dynamic smem 66KB.
// ---------------------------------------------------------------------------
#define LN_PITCH 517
#define LN_SMEM  (32 * LN_PITCH * 4)     // 66176 B

__global__ __launch_bounds__(256)
void ln_kernel(const __half* __restrict__ X, const float* __restrict__ gamma,
               const float* __restrict__ beta, float* __restrict__ out)
{
    extern __shared__ float sm[];

    const int nb   = blockIdx.x * 32;
    const int warp = threadIdx.x >> 5;
    const int lane = threadIdx.x & 31;

    for (int r = warp; r < 32; r += 8) {
        const int n = nb + r;
        const __half* row = X + (size_t)n * 512;
        float v[16];
        float s = 0.f;
#pragma unroll
        for (int j = 0; j < 16; j++) { v[j] = __half2float(row[lane + 32 * j]); s += v[j]; }
#pragma unroll
        for (int o = 16; o > 0; o >>= 1) s += __shfl_xor_sync(0xffffffffu, s, o);
        const float mu = s * (1.f / 512.f);
        float q = 0.f;
#pragma unroll
        for (int j = 0; j < 16; j++) { float d = v[j] - mu; q += d * d; }
#pragma unroll
        for (int o = 16; o > 0; o >>= 1) q += __shfl_xor_sync(0xffffffffu, q, o);
        const float rstd = rsqrtf(q * (1.f / 512.f) + 1e-5f);
#pragma unroll
        for (int j = 0; j < 16; j++) {
            const int o = lane + 32 * j;
            sm[r * LN_PITCH + o] = (v[j] - mu) * rstd * gamma[o] + beta[o];
        }
    }
    __syncthreads();

    const int i  = threadIdx.x & 31;     // position within the 32
    const int ob = threadIdx.x >> 5;     // 0..7
    for (int o = ob; o < 512; o += 8)
        out[(size_t)o * 16384 + nb + i] = sm[i * LN_PITCH + o];
}

// ---------------------------------------------------------------------------
extern "C" void kernel_launch(void* const* d_in, const int* in_sizes, int n_in,
                              void* d_out, int out_size)
{
    const float* low   = (const float*)d_in[0];
    const float* guide = (const float*)d_in[1];
    const float* Wq    = (const float*)d_in[2];
    const float* Wk    = (const float*)d_in[3];
    const float* Wv    = (const float*)d_in[4];
    const float* Wm    = (const float*)d_in[5];
    const float* gamma = (const float*)d_in[6];
    const float* beta  = (const float*)d_in[7];
    float* out = (float*)d_out;

    __half *Af, *Lf, *Whi, *Q, *K, *V;
    cudaGetSymbolAddress((void**)&Af,  g_Af);
    cudaGetSymbolAddress((void**)&Lf,  g_Lf);
    cudaGetSymbolAddress((void**)&Whi, g_Whi);
    cudaGetSymbolAddress((void**)&Q,   g_Q);
    cudaGetSymbolAddress((void**)&K,   g_K);
    cudaGetSymbolAddress((void**)&V,   g_V);

    const int W_ELEMS = DMODEL * DMODEL;              // 262144
    const int GEMM_SMEM = NSTAGE * STAGE_B;           // 73728

    cudaFuncSetAttribute(mma_gemm, cudaFuncAttributeMaxDynamicSharedMemorySize,
                         GEMM_SMEM);
    cudaFuncSetAttribute(ln_kernel, cudaFuncAttributeMaxDynamicSharedMemorySize,
                         LN_SMEM);

    // ALL conversions in one launch
    conv_all<<<5376, 256>>>(guide, low,
                            (const float4*)Wq, (const float4*)Wk,
                            (const float4*)Wv, (const float4*)Wm,
                            Af, Lf, Whi);

    // Q, K, V projections in ONE launch (1 MMA per k16), fp16 outputs
    {
        GemmArgs gq = { Af, Whi,               Q, 128 };
        GemmArgs gk = { Lf, Whi + 1 * W_ELEMS, K, 8 };
        GemmArgs gv = { Lf, Whi + 2 * W_ELEMS, V, 8 };
        mma_gemm<<<dim3(4, 128, 3), 128, GEMM_SMEM>>>(gq, gk, gv);
    }

    // Windowed attention -> fp16 msg directly into Af (guide no longer needed)
    attn_kernel<<<dim3(32, 32), 256>>>(Q, K, V, Af);

    // M2 = msg @ Wm^T, fp16 out into g_Q (Q is dead after attn)
    {
        GemmArgs gm = { Af, Whi + 3 * W_ELEMS, Q, 128 };
        mma_gemm<<<dim3(4, 128, 1), 128, GEMM_SMEM>>>(gm, gm, gm);
    }

    // LayerNorm (fp16 in, fp32 math, 32 pos/block) + channel-major output
    ln_kernel<<<512, 256, LN_SMEM>>>(Q, gamma, beta, out);
}